// round 4
// baseline (speedup 1.0000x reference)
#include <cuda_runtime.h>
#include <math.h>
#include <stdint.h>

// Problem constants
#define BB     32
#define N_PER_ 2000
#define E_PER_ 16000
#define HH     256
#define EFD    20
#define ETN    3
#define CC     100
#define NN     (BB * N_PER_)     // 64000
#define EE     (BB * E_PER_)     // 512000

// ---------------- scratch (static device globals; no runtime alloc) -------
__device__ float  d_A[HH * HH];            // Wl^T @ Wr
__device__ float  d_G[(size_t)NN * HH];    // h @ A   (65.5 MB)
__device__ float  d_wk2[ETN][HH];          // Wl^T K2_t
__device__ float  d_wu[HH];                // Wr^T bl
__device__ float  d_wv[HH];                // Wl^T br
__device__ float  d_consts[ETN];           // bl.K2_t + bl.br
__device__ float4 d_aux[NN];               // (p0+v+c0, p1+v+c1, p2+v+c2, u)
__device__ float2 d_S[NN];                 // (sum exp, sum scores*exp)
__device__ float  d_lossPart[BB];
__device__ float  d_logitsScratch[BB * CC];

// ---------------- prep: gelu(edge_emb), K2 table, folded bias vectors -----
__global__ void prep_kernel(const float* __restrict__ Wl, const float* __restrict__ bl,
                            const float* __restrict__ Wr, const float* __restrict__ br,
                            const float* __restrict__ We, const float* __restrict__ be,
                            const float* __restrict__ eemb) {
    __shared__ float s_ef[ETN][EFD];
    __shared__ float s_K2[ETN][HH];
    __shared__ float s_bl[HH], s_br[HH];
    int tid = threadIdx.x;  // 256 threads

    if (tid < ETN * EFD) {
        float x = eemb[tid];
        s_ef[tid / EFD][tid % EFD] = 0.5f * x * (1.0f + erff(x * 0.70710678118654752f));
    }
    s_bl[tid] = bl[tid];
    s_br[tid] = br[tid];
    __syncthreads();

    // K2[t][i] = be[i] + sum_j We[i][j] * gelu_ef[t][j]
    float bei = be[tid];
    #pragma unroll
    for (int t = 0; t < ETN; t++) {
        float a = bei;
        #pragma unroll
        for (int j = 0; j < EFD; j++) a += We[tid * EFD + j] * s_ef[t][j];
        s_K2[t][tid] = a;
    }
    __syncthreads();

    // wk2[t][i] = sum_k Wl[k][i]*K2[t][k];  wv[i]=sum_k Wl[k][i]*br[k];  wu[i]=sum_k Wr[k][i]*bl[k]
    float p0 = 0.f, p1 = 0.f, p2 = 0.f, v = 0.f, u = 0.f;
    for (int k = 0; k < HH; k++) {
        float wl = Wl[k * HH + tid];
        float wr = Wr[k * HH + tid];
        p0 += wl * s_K2[0][k];
        p1 += wl * s_K2[1][k];
        p2 += wl * s_K2[2][k];
        v  += wl * s_br[k];
        u  += wr * s_bl[k];
    }
    d_wk2[0][tid] = p0;
    d_wk2[1][tid] = p1;
    d_wk2[2][tid] = p2;
    d_wv[tid] = v;
    d_wu[tid] = u;

    if (tid < ETN) {
        float r = 0.f, bb2 = 0.f;
        for (int k = 0; k < HH; k++) {
            r   += s_bl[k] * s_K2[tid][k];
            bb2 += s_bl[k] * s_br[k];
        }
        d_consts[tid] = r + bb2;
    }
}

// ---------------- A = Wl^T @ Wr  (256x256) --------------------------------
__global__ void matA_kernel(const float* __restrict__ Wl, const float* __restrict__ Wr) {
    __shared__ float col[HH];
    int i = blockIdx.x;   // output row
    int j = threadIdx.x;  // output col
    col[j] = Wl[j * HH + i];
    __syncthreads();
    float acc = 0.f;
    #pragma unroll 8
    for (int k = 0; k < HH; k++) acc = fmaf(col[k], Wr[k * HH + j], acc);
    d_A[i * HH + j] = acc;
}

// ---------------- aux per-node table + zero S -----------------------------
// one warp per node; grid = NN/8 blocks of 256 threads
__global__ void aux_kernel(const float* __restrict__ emb) {
    __shared__ float4 w[5][64];
    __shared__ float  sc[ETN];
    int tid = threadIdx.x;
    if (tid < 64) {
        w[0][tid] = ((const float4*)d_wk2[0])[tid];
        w[1][tid] = ((const float4*)d_wk2[1])[tid];
        w[2][tid] = ((const float4*)d_wk2[2])[tid];
        w[3][tid] = ((const float4*)d_wv)[tid];
        w[4][tid] = ((const float4*)d_wu)[tid];
    }
    if (tid < ETN) sc[tid] = d_consts[tid];
    __syncthreads();

    int warp = tid >> 5, lane = tid & 31;
    int n = blockIdx.x * 8 + warp;   // exact: NN/8 blocks
    const float4* hp = (const float4*)(emb + (size_t)n * HH);
    float4 h0 = hp[lane];
    float4 h1 = hp[32 + lane];

    float acc[5];
    #pragma unroll
    for (int q = 0; q < 5; q++) {
        float4 a = w[q][lane];
        float4 b = w[q][32 + lane];
        acc[q] = h0.x * a.x + h0.y * a.y + h0.z * a.z + h0.w * a.w
               + h1.x * b.x + h1.y * b.y + h1.z * b.z + h1.w * b.w;
    }
    #pragma unroll
    for (int o = 16; o > 0; o >>= 1) {
        #pragma unroll
        for (int q = 0; q < 5; q++) acc[q] += __shfl_xor_sync(0xffffffffu, acc[q], o);
    }
    if (lane == 0) {
        d_aux[n] = make_float4(acc[0] + acc[3] + sc[0],
                               acc[1] + acc[3] + sc[1],
                               acc[2] + acc[3] + sc[2],
                               acc[4]);
        d_S[n] = make_float2(0.f, 0.f);
    }
}

// ---------------- G = h @ A  (64000x256 @ 256x256), tiled SGEMM ------------
#define BM 128
#define BN 128
#define BKk 16
#define SPAD 4

__global__ __launch_bounds__(256, 2)
void gemm_kernel(const float* __restrict__ Hm) {
    __shared__ float As[BKk][BM + SPAD];  // transposed h tile
    __shared__ float Bs[BKk][BN];
    int bx = blockIdx.x, by = blockIdx.y;
    int tid = threadIdx.x;
    int tx = tid & 15, ty = tid >> 4;

    const float* hBase = Hm + (size_t)bx * BM * HH;
    const float* aBase = d_A + by * BN;

    float acc[8][8];
    #pragma unroll
    for (int m = 0; m < 8; m++)
        #pragma unroll
        for (int n = 0; n < 8; n++) acc[m][n] = 0.f;

    int lr = tid >> 2;          // 0..63  (h-tile row)
    int lc = (tid & 3) * 4;     // 0,4,8,12 (k offset)
    int ar = tid >> 5;          // 0..7   (A-tile row)
    int ac = (tid & 31) * 4;    // 0..124 (A-tile col)

    for (int k0 = 0; k0 < HH; k0 += BKk) {
        float4 v0 = *(const float4*)(hBase + (size_t)lr * HH + k0 + lc);
        float4 v1 = *(const float4*)(hBase + (size_t)(lr + 64) * HH + k0 + lc);
        float4 w0 = *(const float4*)(aBase + (size_t)(k0 + ar) * HH + ac);
        float4 w1 = *(const float4*)(aBase + (size_t)(k0 + ar + 8) * HH + ac);

        __syncthreads();
        As[lc + 0][lr] = v0.x; As[lc + 1][lr] = v0.y; As[lc + 2][lr] = v0.z; As[lc + 3][lr] = v0.w;
        As[lc + 0][lr + 64] = v1.x; As[lc + 1][lr + 64] = v1.y;
        As[lc + 2][lr + 64] = v1.z; As[lc + 3][lr + 64] = v1.w;
        *(float4*)&Bs[ar][ac]     = w0;
        *(float4*)&Bs[ar + 8][ac] = w1;
        __syncthreads();

        #pragma unroll
        for (int kk = 0; kk < BKk; kk++) {
            float4 a0 = *(const float4*)&As[kk][ty * 8];
            float4 a1 = *(const float4*)&As[kk][ty * 8 + 4];
            float4 b0 = *(const float4*)&Bs[kk][tx * 8];
            float4 b1 = *(const float4*)&Bs[kk][tx * 8 + 4];
            float a[8] = {a0.x, a0.y, a0.z, a0.w, a1.x, a1.y, a1.z, a1.w};
            float b[8] = {b0.x, b0.y, b0.z, b0.w, b1.x, b1.y, b1.z, b1.w};
            #pragma unroll
            for (int m = 0; m < 8; m++)
                #pragma unroll
                for (int n = 0; n < 8; n++)
                    acc[m][n] = fmaf(a[m], b[n], acc[m][n]);
        }
    }

    float* gp = d_G + (size_t)(bx * BM + ty * 8) * HH + by * BN + tx * 8;
    #pragma unroll
    for (int m = 0; m < 8; m++) {
        float4 o0 = make_float4(acc[m][0], acc[m][1], acc[m][2], acc[m][3]);
        float4 o1 = make_float4(acc[m][4], acc[m][5], acc[m][6], acc[m][7]);
        *(float4*)(gp + (size_t)m * HH)     = o0;
        *(float4*)(gp + (size_t)m * HH + 4) = o1;
    }
}

// ---------------- edge pass: alpha -> exp -> atomic segment sums ----------
// one warp per edge; grid = EE/8 blocks of 256 threads
__global__ void edge_kernel(const float* __restrict__ emb, const float* __restrict__ scores,
                            const int* __restrict__ src, const int* __restrict__ dst,
                            const int* __restrict__ et) {
    int gw = blockIdx.x * 8 + (threadIdx.x >> 5);
    int lane = threadIdx.x & 31;
    int s = __ldg(src + gw);
    int d = __ldg(dst + gw);
    int t = __ldg(et + gw);

    const float4* gq = (const float4*)(d_G + (size_t)d * HH);
    const float4* hs = (const float4*)(emb + (size_t)s * HH);
    float4 a0 = gq[lane], a1 = gq[32 + lane];
    float4 b0 = hs[lane], b1 = hs[32 + lane];
    float acc = a0.x * b0.x + a0.y * b0.y + a0.z * b0.z + a0.w * b0.w
              + a1.x * b1.x + a1.y * b1.y + a1.z * b1.z + a1.w * b1.w;
    #pragma unroll
    for (int o = 16; o > 0; o >>= 1) acc += __shfl_xor_sync(0xffffffffu, acc, o);

    if (lane == 0) {
        float4 ad = d_aux[d];
        float pv = (t == 0) ? ad.x : ((t == 1) ? ad.y : ad.z);
        float u  = d_aux[s].w;
        float alpha = (acc + pv + u) * 0.0625f;  // / sqrt(256)
        float ex = expf(alpha);
        atomicAdd(&d_S[d].x, ex);
        atomicAdd(&d_S[d].y, __ldg(scores + s) * ex);
    }
}

// ---------------- per-graph logits + log-softmax + CE ---------------------
__global__ void logits_kernel(const int* __restrict__ cand, const int* __restrict__ label,
                              float* __restrict__ outLogits) {
    __shared__ float sl[CC];
    __shared__ float red[128];
    int b = blockIdx.x, tid = threadIdx.x;

    float logit = 0.f;
    if (tid < CC) {
        int node = cand[b * CC + tid];
        float2 s = d_S[node];
        logit = (s.x > 0.f) ? (s.y / s.x) : 0.f;
        sl[tid] = logit;
        outLogits[b * CC + tid] = logit;
    }
    red[tid] = (tid < CC) ? logit : -3.4e38f;
    __syncthreads();
    for (int st = 64; st > 0; st >>= 1) {
        if (tid < st) red[tid] = fmaxf(red[tid], red[tid + st]);
        __syncthreads();
    }
    float mx = red[0];
    __syncthreads();
    red[tid] = (tid < CC) ? expf(logit - mx) : 0.f;
    __syncthreads();
    for (int st = 64; st > 0; st >>= 1) {
        if (tid < st) red[tid] += red[tid + st];
        __syncthreads();
    }
    if (tid == 0) {
        int lab = label[b];
        d_lossPart[b] = -(sl[lab] - mx - logf(red[0]));
    }
}

__global__ void loss_kernel(float* __restrict__ outLoss) {
    float v = d_lossPart[threadIdx.x];  // 32 threads == BB
    #pragma unroll
    for (int o = 16; o > 0; o >>= 1) v += __shfl_xor_sync(0xffffffffu, v, o);
    if (threadIdx.x == 0) outLoss[0] = v;
}

// ---------------- launch --------------------------------------------------
extern "C" void kernel_launch(void* const* d_in, const int* in_sizes, int n_in,
                              void* d_out, int out_size) {
    const float* emb    = (const float*)d_in[0];
    const float* scores = (const float*)d_in[1];
    const float* Wl     = (const float*)d_in[2];
    const float* bl     = (const float*)d_in[3];
    const float* Wr     = (const float*)d_in[4];
    const float* br     = (const float*)d_in[5];
    const float* We     = (const float*)d_in[6];
    const float* be     = (const float*)d_in[7];
    const float* eemb   = (const float*)d_in[8];
    const int*   src    = (const int*)d_in[9];
    const int*   dst    = (const int*)d_in[10];
    const int*   et     = (const int*)d_in[11];
    const int*   cand   = (const int*)d_in[12];
    const int*   label  = (const int*)d_in[13];

    float* out = (float*)d_out;
    float* lossPtr;
    float* logitsPtr;
    if (out_size >= BB * CC + 1) {            // [loss, logits...] (tuple order)
        lossPtr = out;
        logitsPtr = out + 1;
    } else if (out_size == BB * CC) {         // logits only
        lossPtr = nullptr;
        logitsPtr = out;
    } else {                                  // loss only
        lossPtr = out;
        void* p = nullptr;
        cudaGetSymbolAddress(&p, d_logitsScratch);
        logitsPtr = (float*)p;
    }

    prep_kernel<<<1, HH>>>(Wl, bl, Wr, br, We, be, eemb);
    matA_kernel<<<HH, HH>>>(Wl, Wr);
    aux_kernel<<<NN / 8, 256>>>(emb);
    gemm_kernel<<<dim3(NN / BM, HH / BN), 256>>>(emb);
    edge_kernel<<<EE / 8, 256>>>(emb, scores, src, dst, et);
    logits_kernel<<<BB, 128>>>(cand, label, logitsPtr);
    if (lossPtr) loss_kernel<<<1, 32>>>(lossPtr);
}

// round 7
// speedup vs baseline: 1.0809x; 1.0809x over previous
#include <cuda_runtime.h>
#include <math.h>
#include <stdint.h>

// Problem constants
#define BB     32
#define N_PER_ 2000
#define E_PER_ 16000
#define HH     256
#define EFD    20
#define ETN    3
#define CC     100
#define NN     (BB * N_PER_)     // 64000
#define EE     (BB * E_PER_)     // 512000

typedef unsigned long long u64;

// ---------------- f32x2 packed helpers (Blackwell FFMA2) -------------------
__device__ __forceinline__ void ffma2(u64& acc, u64 a, u64 b) {
    asm("fma.rn.f32x2 %0, %1, %2, %0;" : "+l"(acc) : "l"(a), "l"(b));
}
__device__ __forceinline__ u64 pack2(float lo, float hi) {
    u64 r; asm("mov.b64 %0, {%1, %2};" : "=l"(r) : "f"(lo), "f"(hi)); return r;
}
__device__ __forceinline__ void unpack2(u64 v, float& lo, float& hi) {
    asm("mov.b64 {%0, %1}, %2;" : "=f"(lo), "=f"(hi) : "l"(v));
}

// ---------------- scratch (static device globals; no runtime alloc) -------
__device__ float  d_A[HH * HH];            // Wl^T @ Wr
__device__ float  d_G[(size_t)NN * HH];    // h @ A   (65.5 MB)
__device__ float  d_wk2[ETN][HH];          // Wl^T K2_t
__device__ float  d_wu[HH];                // Wr^T bl
__device__ float  d_wv[HH];                // Wl^T br
__device__ float  d_consts[ETN];           // bl.K2_t + bl.br
__device__ float4 d_aux[NN];               // (p0+v+c0, p1+v+c1, p2+v+c2, u)
__device__ float2 d_S[NN];                 // (sum exp, sum scores*exp)
__device__ float  d_lossPart[BB];
__device__ float  d_logitsScratch[BB * CC];

// ---------------- prep: gelu(edge_emb), K2 table, folded bias vectors -----
__global__ void prep_kernel(const float* __restrict__ Wl, const float* __restrict__ bl,
                            const float* __restrict__ Wr, const float* __restrict__ br,
                            const float* __restrict__ We, const float* __restrict__ be,
                            const float* __restrict__ eemb) {
    __shared__ float s_ef[ETN][EFD];
    __shared__ float s_K2[ETN][HH];
    __shared__ float s_bl[HH], s_br[HH];
    int tid = threadIdx.x;  // 256 threads

    if (tid < ETN * EFD) {
        float x = eemb[tid];
        s_ef[tid / EFD][tid % EFD] = 0.5f * x * (1.0f + erff(x * 0.70710678118654752f));
    }
    s_bl[tid] = bl[tid];
    s_br[tid] = br[tid];
    __syncthreads();

    // K2[t][i] = be[i] + sum_j We[i][j] * gelu_ef[t][j]
    float bei = be[tid];
    #pragma unroll
    for (int t = 0; t < ETN; t++) {
        float a = bei;
        #pragma unroll
        for (int j = 0; j < EFD; j++) a += We[tid * EFD + j] * s_ef[t][j];
        s_K2[t][tid] = a;
    }
    __syncthreads();

    // wk2[t][i] = sum_k Wl[k][i]*K2[t][k];  wv[i]=sum_k Wl[k][i]*br[k];  wu[i]=sum_k Wr[k][i]*bl[k]
    float p0 = 0.f, p1 = 0.f, p2 = 0.f, v = 0.f, u = 0.f;
    for (int k = 0; k < HH; k++) {
        float wl = Wl[k * HH + tid];
        float wr = Wr[k * HH + tid];
        p0 += wl * s_K2[0][k];
        p1 += wl * s_K2[1][k];
        p2 += wl * s_K2[2][k];
        v  += wl * s_br[k];
        u  += wr * s_bl[k];
    }
    d_wk2[0][tid] = p0;
    d_wk2[1][tid] = p1;
    d_wk2[2][tid] = p2;
    d_wv[tid] = v;
    d_wu[tid] = u;

    if (tid < ETN) {
        float r = 0.f, bb2 = 0.f;
        for (int k = 0; k < HH; k++) {
            r   += s_bl[k] * s_K2[tid][k];
            bb2 += s_bl[k] * s_br[k];
        }
        d_consts[tid] = r + bb2;
    }
}

// ---------------- A = Wl^T @ Wr  (256x256) --------------------------------
__global__ void matA_kernel(const float* __restrict__ Wl, const float* __restrict__ Wr) {
    __shared__ float col[HH];
    int i = blockIdx.x;   // output row
    int j = threadIdx.x;  // output col
    col[j] = Wl[j * HH + i];
    __syncthreads();
    float acc = 0.f;
    #pragma unroll 8
    for (int k = 0; k < HH; k++) acc = fmaf(col[k], Wr[k * HH + j], acc);
    d_A[i * HH + j] = acc;
}

// ---------------- aux per-node table + zero S -----------------------------
// one warp per node; grid = NN/8 blocks of 256 threads
__global__ void aux_kernel(const float* __restrict__ emb) {
    __shared__ float4 w[5][64];
    __shared__ float  sc[ETN];
    int tid = threadIdx.x;
    if (tid < 64) {
        w[0][tid] = ((const float4*)d_wk2[0])[tid];
        w[1][tid] = ((const float4*)d_wk2[1])[tid];
        w[2][tid] = ((const float4*)d_wk2[2])[tid];
        w[3][tid] = ((const float4*)d_wv)[tid];
        w[4][tid] = ((const float4*)d_wu)[tid];
    }
    if (tid < ETN) sc[tid] = d_consts[tid];
    __syncthreads();

    int warp = tid >> 5, lane = tid & 31;
    int n = blockIdx.x * 8 + warp;   // exact: NN/8 blocks
    const float4* hp = (const float4*)(emb + (size_t)n * HH);
    float4 h0 = hp[lane];
    float4 h1 = hp[32 + lane];

    float acc[5];
    #pragma unroll
    for (int q = 0; q < 5; q++) {
        float4 a = w[q][lane];
        float4 b = w[q][32 + lane];
        acc[q] = h0.x * a.x + h0.y * a.y + h0.z * a.z + h0.w * a.w
               + h1.x * b.x + h1.y * b.y + h1.z * b.z + h1.w * b.w;
    }
    #pragma unroll
    for (int o = 16; o > 0; o >>= 1) {
        #pragma unroll
        for (int q = 0; q < 5; q++) acc[q] += __shfl_xor_sync(0xffffffffu, acc[q], o);
    }
    if (lane == 0) {
        d_aux[n] = make_float4(acc[0] + acc[3] + sc[0],
                               acc[1] + acc[3] + sc[1],
                               acc[2] + acc[3] + sc[2],
                               acc[4]);
        d_S[n] = make_float2(0.f, 0.f);
    }
}

// ---------------- G = h @ A  (64000x256 @ 256x256), f32x2 SGEMM ------------
#define BM 128
#define BN 128
#define BKk 16
#define SPAD 4

__global__ __launch_bounds__(256, 2)
void gemm_kernel(const float* __restrict__ Hm) {
    __shared__ float As[BKk][BM + SPAD];  // transposed h tile
    __shared__ float Bs[BKk][BN];
    int bx = blockIdx.x, by = blockIdx.y;
    int tid = threadIdx.x;
    int tx = tid & 15, ty = tid >> 4;

    const float* hBase = Hm + (size_t)bx * BM * HH;
    const float* aBase = d_A + by * BN;

    // acc[m][j] = packed pair (C[m][2j], C[m][2j+1])
    u64 acc[8][4];
    #pragma unroll
    for (int m = 0; m < 8; m++)
        #pragma unroll
        for (int j = 0; j < 4; j++) acc[m][j] = 0ULL;

    int lr = tid >> 2;          // 0..63  (h-tile row)
    int lc = (tid & 3) * 4;     // 0,4,8,12 (k offset)
    int ar = tid >> 5;          // 0..7   (A-tile row)
    int ac = (tid & 31) * 4;    // 0..124 (A-tile col)

    for (int k0 = 0; k0 < HH; k0 += BKk) {
        float4 v0 = *(const float4*)(hBase + (size_t)lr * HH + k0 + lc);
        float4 v1 = *(const float4*)(hBase + (size_t)(lr + 64) * HH + k0 + lc);
        float4 w0 = *(const float4*)(aBase + (size_t)(k0 + ar) * HH + ac);
        float4 w1 = *(const float4*)(aBase + (size_t)(k0 + ar + 8) * HH + ac);

        __syncthreads();
        As[lc + 0][lr] = v0.x; As[lc + 1][lr] = v0.y; As[lc + 2][lr] = v0.z; As[lc + 3][lr] = v0.w;
        As[lc + 0][lr + 64] = v1.x; As[lc + 1][lr + 64] = v1.y;
        As[lc + 2][lr + 64] = v1.z; As[lc + 3][lr + 64] = v1.w;
        *(float4*)&Bs[ar][ac]     = w0;
        *(float4*)&Bs[ar + 8][ac] = w1;
        __syncthreads();

        #pragma unroll
        for (int kk = 0; kk < BKk; kk++) {
            float4 a0 = *(const float4*)&As[kk][ty * 8];
            float4 a1 = *(const float4*)&As[kk][ty * 8 + 4];
            // b as natural packed pairs: (b0,b1) (b2,b3) (b4,b5) (b6,b7)
            ulonglong2 bp0 = *(const ulonglong2*)&Bs[kk][tx * 8];
            ulonglong2 bp1 = *(const ulonglong2*)&Bs[kk][tx * 8 + 4];
            u64 b[4] = {bp0.x, bp0.y, bp1.x, bp1.y};
            float a[8] = {a0.x, a0.y, a0.z, a0.w, a1.x, a1.y, a1.z, a1.w};
            #pragma unroll
            for (int m = 0; m < 8; m++) {
                u64 ad = pack2(a[m], a[m]);   // broadcast a[m] into both lanes
                #pragma unroll
                for (int j = 0; j < 4; j++) ffma2(acc[m][j], ad, b[j]);
            }
        }
    }

    float* gp = d_G + (size_t)(bx * BM + ty * 8) * HH + by * BN + tx * 8;
    #pragma unroll
    for (int m = 0; m < 8; m++) {
        float4 o0, o1;
        unpack2(acc[m][0], o0.x, o0.y);
        unpack2(acc[m][1], o0.z, o0.w);
        unpack2(acc[m][2], o1.x, o1.y);
        unpack2(acc[m][3], o1.z, o1.w);
        *(float4*)(gp + (size_t)m * HH)     = o0;
        *(float4*)(gp + (size_t)m * HH + 4) = o1;
    }
}

// ---------------- edge pass: alpha -> exp -> atomic segment sums ----------
// one warp per edge; grid = EE/8 blocks of 256 threads
__global__ void edge_kernel(const float* __restrict__ emb, const float* __restrict__ scores,
                            const int* __restrict__ src, const int* __restrict__ dst,
                            const int* __restrict__ et) {
    int gw = blockIdx.x * 8 + (threadIdx.x >> 5);
    int lane = threadIdx.x & 31;
    int s = __ldg(src + gw);
    int d = __ldg(dst + gw);
    int t = __ldg(et + gw);

    const float4* gq = (const float4*)(d_G + (size_t)d * HH);
    const float4* hs = (const float4*)(emb + (size_t)s * HH);
    float4 a0 = gq[lane], a1 = gq[32 + lane];
    float4 b0 = hs[lane], b1 = hs[32 + lane];
    float acc = a0.x * b0.x + a0.y * b0.y + a0.z * b0.z + a0.w * b0.w
              + a1.x * b1.x + a1.y * b1.y + a1.z * b1.z + a1.w * b1.w;
    #pragma unroll
    for (int o = 16; o > 0; o >>= 1) acc += __shfl_xor_sync(0xffffffffu, acc, o);

    if (lane == 0) {
        float4 ad = d_aux[d];
        float pv = (t == 0) ? ad.x : ((t == 1) ? ad.y : ad.z);
        float u  = d_aux[s].w;
        float alpha = (acc + pv + u) * 0.0625f;  // / sqrt(256)
        float ex = expf(alpha);
        atomicAdd(&d_S[d].x, ex);
        atomicAdd(&d_S[d].y, __ldg(scores + s) * ex);
    }
}

// ---------------- per-graph logits + log-softmax + CE ---------------------
__global__ void logits_kernel(const int* __restrict__ cand, const int* __restrict__ label,
                              float* __restrict__ outLogits) {
    __shared__ float sl[CC];
    __shared__ float red[128];
    int b = blockIdx.x, tid = threadIdx.x;

    float logit = 0.f;
    if (tid < CC) {
        int node = cand[b * CC + tid];
        float2 s = d_S[node];
        logit = (s.x > 0.f) ? (s.y / s.x) : 0.f;
        sl[tid] = logit;
        outLogits[b * CC + tid] = logit;
    }
    red[tid] = (tid < CC) ? logit : -3.4e38f;
    __syncthreads();
    for (int st = 64; st > 0; st >>= 1) {
        if (tid < st) red[tid] = fmaxf(red[tid], red[tid + st]);
        __syncthreads();
    }
    float mx = red[0];
    __syncthreads();
    red[tid] = (tid < CC) ? expf(logit - mx) : 0.f;
    __syncthreads();
    for (int st = 64; st > 0; st >>= 1) {
        if (tid < st) red[tid] += red[tid + st];
        __syncthreads();
    }
    if (tid == 0) {
        int lab = label[b];
        d_lossPart[b] = -(sl[lab] - mx - logf(red[0]));
    }
}

__global__ void loss_kernel(float* __restrict__ outLoss) {
    float v = d_lossPart[threadIdx.x];  // 32 threads == BB
    #pragma unroll
    for (int o = 16; o > 0; o >>= 1) v += __shfl_xor_sync(0xffffffffu, v, o);
    if (threadIdx.x == 0) outLoss[0] = v;
}

// ---------------- launch --------------------------------------------------
extern "C" void kernel_launch(void* const* d_in, const int* in_sizes, int n_in,
                              void* d_out, int out_size) {
    const float* emb    = (const float*)d_in[0];
    const float* scores = (const float*)d_in[1];
    const float* Wl     = (const float*)d_in[2];
    const float* bl     = (const float*)d_in[3];
    const float* Wr     = (const float*)d_in[4];
    const float* br     = (const float*)d_in[5];
    const float* We     = (const float*)d_in[6];
    const float* be     = (const float*)d_in[7];
    const float* eemb   = (const float*)d_in[8];
    const int*   src    = (const int*)d_in[9];
    const int*   dst    = (const int*)d_in[10];
    const int*   et     = (const int*)d_in[11];
    const int*   cand   = (const int*)d_in[12];
    const int*   label  = (const int*)d_in[13];

    float* out = (float*)d_out;
    float* lossPtr;
    float* logitsPtr;
    if (out_size >= BB * CC + 1) {            // [loss, logits...] (tuple order)
        lossPtr = out;
        logitsPtr = out + 1;
    } else if (out_size == BB * CC) {         // logits only
        lossPtr = nullptr;
        logitsPtr = out;
    } else {                                  // loss only
        lossPtr = out;
        void* p = nullptr;
        cudaGetSymbolAddress(&p, d_logitsScratch);
        logitsPtr = (float*)p;
    }

    prep_kernel<<<1, HH>>>(Wl, bl, Wr, br, We, be, eemb);
    matA_kernel<<<HH, HH>>>(Wl, Wr);
    aux_kernel<<<NN / 8, 256>>>(emb);
    gemm_kernel<<<dim3(NN / BM, HH / BN), 256>>>(emb);
    edge_kernel<<<EE / 8, 256>>>(emb, scores, src, dst, et);
    logits_kernel<<<BB, 128>>>(cand, label, logitsPtr);
    if (lossPtr) loss_kernel<<<1, 32>>>(lossPtr);
}

// round 9
// speedup vs baseline: 1.1575x; 1.0709x over previous
#include <cuda_runtime.h>
#include <math.h>
#include <stdint.h>

// Problem constants
#define BB     32
#define N_PER_ 2000
#define E_PER_ 16000
#define HH     256
#define EFD    20
#define ETN    3
#define CC     100
#define NN     (BB * N_PER_)     // 64000
#define EE     (BB * E_PER_)     // 512000

typedef unsigned long long u64;

// ---------------- f32x2 packed helpers (Blackwell FFMA2) -------------------
__device__ __forceinline__ void ffma2(u64& acc, u64 a, u64 b) {
    asm("fma.rn.f32x2 %0, %1, %2, %0;" : "+l"(acc) : "l"(a), "l"(b));
}
__device__ __forceinline__ u64 pack2(float lo, float hi) {
    u64 r; asm("mov.b64 %0, {%1, %2};" : "=l"(r) : "f"(lo), "f"(hi)); return r;
}
__device__ __forceinline__ void unpack2(u64 v, float& lo, float& hi) {
    asm("mov.b64 {%0, %1}, %2;" : "=f"(lo), "=f"(hi) : "l"(v));
}

// ---------------- scratch (static device globals; no runtime alloc) -------
__device__ float  d_A[HH * HH];            // Wl^T @ Wr
__device__ float  d_G[(size_t)NN * HH];    // h @ A   (65.5 MB)
__device__ float  d_wk2[ETN][HH];          // Wl^T K2_t
__device__ float  d_wu[HH];                // Wr^T bl
__device__ float  d_wv[HH];                // Wl^T br
__device__ float  d_consts[ETN];           // bl.K2_t + bl.br
__device__ float4 d_aux[NN];               // (p0+v+c0, p1+v+c1, p2+v+c2, u)
__device__ float2 d_S[NN];                 // (sum exp, sum scores*exp)
__device__ float  d_lossPart[BB];
__device__ float  d_logitsScratch[BB * CC];

// ---------------- prep: gelu(edge_emb), K2 table, folded bias vectors -----
__global__ void prep_kernel(const float* __restrict__ Wl, const float* __restrict__ bl,
                            const float* __restrict__ Wr, const float* __restrict__ br,
                            const float* __restrict__ We, const float* __restrict__ be,
                            const float* __restrict__ eemb) {
    __shared__ float s_ef[ETN][EFD];
    __shared__ float s_K2[ETN][HH];
    __shared__ float s_bl[HH], s_br[HH];
    int tid = threadIdx.x;  // 256 threads

    if (tid < ETN * EFD) {
        float x = eemb[tid];
        s_ef[tid / EFD][tid % EFD] = 0.5f * x * (1.0f + erff(x * 0.70710678118654752f));
    }
    s_bl[tid] = bl[tid];
    s_br[tid] = br[tid];
    __syncthreads();

    // K2[t][i] = be[i] + sum_j We[i][j] * gelu_ef[t][j]
    float bei = be[tid];
    #pragma unroll
    for (int t = 0; t < ETN; t++) {
        float a = bei;
        #pragma unroll
        for (int j = 0; j < EFD; j++) a += We[tid * EFD + j] * s_ef[t][j];
        s_K2[t][tid] = a;
    }
    __syncthreads();

    // wk2[t][i] = sum_k Wl[k][i]*K2[t][k];  wv[i]=sum_k Wl[k][i]*br[k];  wu[i]=sum_k Wr[k][i]*bl[k]
    float p0 = 0.f, p1 = 0.f, p2 = 0.f, v = 0.f, u = 0.f;
    for (int k = 0; k < HH; k++) {
        float wl = Wl[k * HH + tid];
        float wr = Wr[k * HH + tid];
        p0 += wl * s_K2[0][k];
        p1 += wl * s_K2[1][k];
        p2 += wl * s_K2[2][k];
        v  += wl * s_br[k];
        u  += wr * s_bl[k];
    }
    d_wk2[0][tid] = p0;
    d_wk2[1][tid] = p1;
    d_wk2[2][tid] = p2;
    d_wv[tid] = v;
    d_wu[tid] = u;

    if (tid < ETN) {
        float r = 0.f, bb2 = 0.f;
        for (int k = 0; k < HH; k++) {
            r   += s_bl[k] * s_K2[tid][k];
            bb2 += s_bl[k] * s_br[k];
        }
        d_consts[tid] = r + bb2;
    }
}

// ---------------- A = Wl^T @ Wr  (256x256) --------------------------------
__global__ void matA_kernel(const float* __restrict__ Wl, const float* __restrict__ Wr) {
    __shared__ float col[HH];
    int i = blockIdx.x;   // output row
    int j = threadIdx.x;  // output col
    col[j] = Wl[j * HH + i];
    __syncthreads();
    float acc = 0.f;
    #pragma unroll 8
    for (int k = 0; k < HH; k++) acc = fmaf(col[k], Wr[k * HH + j], acc);
    d_A[i * HH + j] = acc;
}

// ---------------- aux per-node table + zero S -----------------------------
// one warp per node; grid = NN/8 blocks of 256 threads
__global__ void aux_kernel(const float* __restrict__ emb) {
    __shared__ float4 w[5][64];
    __shared__ float  sc[ETN];
    int tid = threadIdx.x;
    if (tid < 64) {
        w[0][tid] = ((const float4*)d_wk2[0])[tid];
        w[1][tid] = ((const float4*)d_wk2[1])[tid];
        w[2][tid] = ((const float4*)d_wk2[2])[tid];
        w[3][tid] = ((const float4*)d_wv)[tid];
        w[4][tid] = ((const float4*)d_wu)[tid];
    }
    if (tid < ETN) sc[tid] = d_consts[tid];
    __syncthreads();

    int warp = tid >> 5, lane = tid & 31;
    int n = blockIdx.x * 8 + warp;   // exact: NN/8 blocks
    const float4* hp = (const float4*)(emb + (size_t)n * HH);
    float4 h0 = hp[lane];
    float4 h1 = hp[32 + lane];

    float acc[5];
    #pragma unroll
    for (int q = 0; q < 5; q++) {
        float4 a = w[q][lane];
        float4 b = w[q][32 + lane];
        acc[q] = h0.x * a.x + h0.y * a.y + h0.z * a.z + h0.w * a.w
               + h1.x * b.x + h1.y * b.y + h1.z * b.z + h1.w * b.w;
    }
    #pragma unroll
    for (int o = 16; o > 0; o >>= 1) {
        #pragma unroll
        for (int q = 0; q < 5; q++) acc[q] += __shfl_xor_sync(0xffffffffu, acc[q], o);
    }
    if (lane == 0) {
        d_aux[n] = make_float4(acc[0] + acc[3] + sc[0],
                               acc[1] + acc[3] + sc[1],
                               acc[2] + acc[3] + sc[2],
                               acc[4]);
        d_S[n] = make_float2(0.f, 0.f);
    }
}

// ---------------- G = h @ A  (64000x256 @ 256x256), f32x2 SGEMM ------------
// Per-thread output columns: {tx*4..tx*4+3} U {64+tx*4..64+tx*4+3}
// -> B-operand LDS reads are 256B-contiguous per warp half (2 wf/load).
#define BM 128
#define BN 128
#define BKk 16
#define SPAD 4

__global__ __launch_bounds__(256, 2)
void gemm_kernel(const float* __restrict__ Hm) {
    __shared__ float As[BKk][BM + SPAD];  // transposed h tile
    __shared__ float Bs[BKk][BN];
    int bx = blockIdx.x, by = blockIdx.y;
    int tid = threadIdx.x;
    int tx = tid & 15, ty = tid >> 4;

    const float* hBase = Hm + (size_t)bx * BM * HH;
    const float* aBase = d_A + by * BN;

    // acc[m][0..1] -> cols tx*4..+3 ; acc[m][2..3] -> cols 64+tx*4..+3
    u64 acc[8][4];
    #pragma unroll
    for (int m = 0; m < 8; m++)
        #pragma unroll
        for (int j = 0; j < 4; j++) acc[m][j] = 0ULL;

    int lr = tid >> 2;          // 0..63  (h-tile row)
    int lc = (tid & 3) * 4;     // 0,4,8,12 (k offset)
    int ar = tid >> 5;          // 0..7   (A-tile row)
    int ac = (tid & 31) * 4;    // 0..124 (A-tile col)

    for (int k0 = 0; k0 < HH; k0 += BKk) {
        float4 v0 = *(const float4*)(hBase + (size_t)lr * HH + k0 + lc);
        float4 v1 = *(const float4*)(hBase + (size_t)(lr + 64) * HH + k0 + lc);
        float4 w0 = *(const float4*)(aBase + (size_t)(k0 + ar) * HH + ac);
        float4 w1 = *(const float4*)(aBase + (size_t)(k0 + ar + 8) * HH + ac);

        __syncthreads();
        As[lc + 0][lr] = v0.x; As[lc + 1][lr] = v0.y; As[lc + 2][lr] = v0.z; As[lc + 3][lr] = v0.w;
        As[lc + 0][lr + 64] = v1.x; As[lc + 1][lr + 64] = v1.y;
        As[lc + 2][lr + 64] = v1.z; As[lc + 3][lr + 64] = v1.w;
        *(float4*)&Bs[ar][ac]     = w0;
        *(float4*)&Bs[ar + 8][ac] = w1;
        __syncthreads();

        #pragma unroll
        for (int kk = 0; kk < BKk; kk++) {
            float4 a0 = *(const float4*)&As[kk][ty * 8];
            float4 a1 = *(const float4*)&As[kk][ty * 8 + 4];
            // contiguous 16B per thread -> 2 wavefronts per warp per load
            ulonglong2 bp0 = *(const ulonglong2*)&Bs[kk][tx * 4];
            ulonglong2 bp1 = *(const ulonglong2*)&Bs[kk][64 + tx * 4];
            u64 b[4] = {bp0.x, bp0.y, bp1.x, bp1.y};
            float a[8] = {a0.x, a0.y, a0.z, a0.w, a1.x, a1.y, a1.z, a1.w};
            #pragma unroll
            for (int m = 0; m < 8; m++) {
                u64 ad = pack2(a[m], a[m]);   // broadcast a[m] into both lanes
                #pragma unroll
                for (int j = 0; j < 4; j++) ffma2(acc[m][j], ad, b[j]);
            }
        }
    }

    float* gp = d_G + (size_t)(bx * BM + ty * 8) * HH + by * BN;
    #pragma unroll
    for (int m = 0; m < 8; m++) {
        float4 o0, o1;
        unpack2(acc[m][0], o0.x, o0.y);
        unpack2(acc[m][1], o0.z, o0.w);
        unpack2(acc[m][2], o1.x, o1.y);
        unpack2(acc[m][3], o1.z, o1.w);
        *(float4*)(gp + (size_t)m * HH + tx * 4)      = o0;
        *(float4*)(gp + (size_t)m * HH + 64 + tx * 4) = o1;
    }
}

// ---------------- edge pass: alpha -> exp -> atomic segment sums ----------
// one warp per edge; grid = EE/8 blocks of 256 threads
__global__ void edge_kernel(const float* __restrict__ emb, const float* __restrict__ scores,
                            const int* __restrict__ src, const int* __restrict__ dst,
                            const int* __restrict__ et) {
    int gw = blockIdx.x * 8 + (threadIdx.x >> 5);
    int lane = threadIdx.x & 31;
    int s = __ldg(src + gw);
    int d = __ldg(dst + gw);
    int t = __ldg(et + gw);

    const float4* gq = (const float4*)(d_G + (size_t)d * HH);
    const float4* hs = (const float4*)(emb + (size_t)s * HH);
    float4 a0 = gq[lane], a1 = gq[32 + lane];
    float4 b0 = hs[lane], b1 = hs[32 + lane];
    float acc = a0.x * b0.x + a0.y * b0.y + a0.z * b0.z + a0.w * b0.w
              + a1.x * b1.x + a1.y * b1.y + a1.z * b1.z + a1.w * b1.w;
    #pragma unroll
    for (int o = 16; o > 0; o >>= 1) acc += __shfl_xor_sync(0xffffffffu, acc, o);

    if (lane == 0) {
        float4 ad = d_aux[d];
        float pv = (t == 0) ? ad.x : ((t == 1) ? ad.y : ad.z);
        float u  = d_aux[s].w;
        float alpha = (acc + pv + u) * 0.0625f;  // / sqrt(256)
        float ex = expf(alpha);
        atomicAdd(&d_S[d].x, ex);
        atomicAdd(&d_S[d].y, __ldg(scores + s) * ex);
    }
}

// ---------------- per-graph logits + log-softmax + CE ---------------------
__global__ void logits_kernel(const int* __restrict__ cand, const int* __restrict__ label,
                              float* __restrict__ outLogits) {
    __shared__ float sl[CC];
    __shared__ float red[128];
    int b = blockIdx.x, tid = threadIdx.x;

    float logit = 0.f;
    if (tid < CC) {
        int node = cand[b * CC + tid];
        float2 s = d_S[node];
        logit = (s.x > 0.f) ? (s.y / s.x) : 0.f;
        sl[tid] = logit;
        outLogits[b * CC + tid] = logit;
    }
    red[tid] = (tid < CC) ? logit : -3.4e38f;
    __syncthreads();
    for (int st = 64; st > 0; st >>= 1) {
        if (tid < st) red[tid] = fmaxf(red[tid], red[tid + st]);
        __syncthreads();
    }
    float mx = red[0];
    __syncthreads();
    red[tid] = (tid < CC) ? expf(logit - mx) : 0.f;
    __syncthreads();
    for (int st = 64; st > 0; st >>= 1) {
        if (tid < st) red[tid] += red[tid + st];
        __syncthreads();
    }
    if (tid == 0) {
        int lab = label[b];
        d_lossPart[b] = -(sl[lab] - mx - logf(red[0]));
    }
}

__global__ void loss_kernel(float* __restrict__ outLoss) {
    float v = d_lossPart[threadIdx.x];  // 32 threads == BB
    #pragma unroll
    for (int o = 16; o > 0; o >>= 1) v += __shfl_xor_sync(0xffffffffu, v, o);
    if (threadIdx.x == 0) outLoss[0] = v;
}

// ---------------- launch --------------------------------------------------
extern "C" void kernel_launch(void* const* d_in, const int* in_sizes, int n_in,
                              void* d_out, int out_size) {
    const float* emb    = (const float*)d_in[0];
    const float* scores = (const float*)d_in[1];
    const float* Wl     = (const float*)d_in[2];
    const float* bl     = (const float*)d_in[3];
    const float* Wr     = (const float*)d_in[4];
    const float* br     = (const float*)d_in[5];
    const float* We     = (const float*)d_in[6];
    const float* be     = (const float*)d_in[7];
    const float* eemb   = (const float*)d_in[8];
    const int*   src    = (const int*)d_in[9];
    const int*   dst    = (const int*)d_in[10];
    const int*   et     = (const int*)d_in[11];
    const int*   cand   = (const int*)d_in[12];
    const int*   label  = (const int*)d_in[13];

    float* out = (float*)d_out;
    float* lossPtr;
    float* logitsPtr;
    if (out_size >= BB * CC + 1) {            // [loss, logits...] (tuple order)
        lossPtr = out;
        logitsPtr = out + 1;
    } else if (out_size == BB * CC) {         // logits only
        lossPtr = nullptr;
        logitsPtr = out;
    } else {                                  // loss only
        lossPtr = out;
        void* p = nullptr;
        cudaGetSymbolAddress(&p, d_logitsScratch);
        logitsPtr = (float*)p;
    }

    prep_kernel<<<1, HH>>>(Wl, bl, Wr, br, We, be, eemb);
    matA_kernel<<<HH, HH>>>(Wl, Wr);
    aux_kernel<<<NN / 8, 256>>>(emb);
    gemm_kernel<<<dim3(NN / BM, HH / BN), 256>>>(emb);
    edge_kernel<<<EE / 8, 256>>>(emb, scores, src, dst, et);
    logits_kernel<<<BB, 128>>>(cand, label, logitsPtr);
    if (lossPtr) loss_kernel<<<1, 32>>>(lossPtr);
}

// round 11
// speedup vs baseline: 1.2379x; 1.0695x over previous
#include <cuda_runtime.h>
#include <math.h>
#include <stdint.h>

// Problem constants
#define BB     32
#define N_PER_ 2000
#define E_PER_ 16000
#define HH     256
#define EFD    20
#define ETN    3
#define CC     100
#define NN     (BB * N_PER_)     // 64000
#define EE     (BB * E_PER_)     // 512000

typedef unsigned long long u64;

// ---------------- f32x2 packed helpers (Blackwell FFMA2) -------------------
__device__ __forceinline__ void ffma2(u64& acc, u64 a, u64 b) {
    asm("fma.rn.f32x2 %0, %1, %2, %0;" : "+l"(acc) : "l"(a), "l"(b));
}
__device__ __forceinline__ u64 pack2(float lo, float hi) {
    u64 r; asm("mov.b64 %0, {%1, %2};" : "=l"(r) : "f"(lo), "f"(hi)); return r;
}
__device__ __forceinline__ void unpack2(u64 v, float& lo, float& hi) {
    asm("mov.b64 {%0, %1}, %2;" : "=f"(lo), "=f"(hi) : "l"(v));
}

// ---------------- cp.async helpers ----------------------------------------
__device__ __forceinline__ void cp_async16(uint32_t smem_addr, const void* gptr) {
    asm volatile("cp.async.cg.shared.global [%0], [%1], 16;"
                 :: "r"(smem_addr), "l"(gptr));
}
#define CP_COMMIT() asm volatile("cp.async.commit_group;" ::: "memory")
#define CP_WAIT0()  asm volatile("cp.async.wait_group 0;" ::: "memory")

// ---------------- scratch (static device globals; no runtime alloc) -------
__device__ float  d_A[HH * HH];            // Wl^T @ Wr
__device__ float  d_G[(size_t)NN * HH];    // h @ A   (65.5 MB)
__device__ float  d_wk2[ETN][HH];          // Wl^T K2_t
__device__ float  d_wu[HH];                // Wr^T bl
__device__ float  d_wv[HH];                // Wl^T br
__device__ float  d_consts[ETN];           // bl.K2_t + bl.br
__device__ float4 d_aux[NN];               // (p0+v+c0, p1+v+c1, p2+v+c2, u)
__device__ float2 d_S[NN];                 // (sum exp, sum scores*exp)
__device__ float  d_lossPart[BB];
__device__ float  d_logitsScratch[BB * CC];

// ---------------- prep: gelu(edge_emb), K2 table, folded bias vectors -----
__global__ void prep_kernel(const float* __restrict__ Wl, const float* __restrict__ bl,
                            const float* __restrict__ Wr, const float* __restrict__ br,
                            const float* __restrict__ We, const float* __restrict__ be,
                            const float* __restrict__ eemb) {
    __shared__ float s_ef[ETN][EFD];
    __shared__ float s_K2[ETN][HH];
    __shared__ float s_bl[HH], s_br[HH];
    int tid = threadIdx.x;  // 256 threads

    if (tid < ETN * EFD) {
        float x = eemb[tid];
        s_ef[tid / EFD][tid % EFD] = 0.5f * x * (1.0f + erff(x * 0.70710678118654752f));
    }
    s_bl[tid] = bl[tid];
    s_br[tid] = br[tid];
    __syncthreads();

    // K2[t][i] = be[i] + sum_j We[i][j] * gelu_ef[t][j]
    float bei = be[tid];
    #pragma unroll
    for (int t = 0; t < ETN; t++) {
        float a = bei;
        #pragma unroll
        for (int j = 0; j < EFD; j++) a += We[tid * EFD + j] * s_ef[t][j];
        s_K2[t][tid] = a;
    }
    __syncthreads();

    // wk2[t][i] = sum_k Wl[k][i]*K2[t][k];  wv[i]=sum_k Wl[k][i]*br[k];  wu[i]=sum_k Wr[k][i]*bl[k]
    float p0 = 0.f, p1 = 0.f, p2 = 0.f, v = 0.f, u = 0.f;
    for (int k = 0; k < HH; k++) {
        float wl = Wl[k * HH + tid];
        float wr = Wr[k * HH + tid];
        p0 += wl * s_K2[0][k];
        p1 += wl * s_K2[1][k];
        p2 += wl * s_K2[2][k];
        v  += wl * s_br[k];
        u  += wr * s_bl[k];
    }
    d_wk2[0][tid] = p0;
    d_wk2[1][tid] = p1;
    d_wk2[2][tid] = p2;
    d_wv[tid] = v;
    d_wu[tid] = u;

    if (tid < ETN) {
        float r = 0.f, bb2 = 0.f;
        for (int k = 0; k < HH; k++) {
            r   += s_bl[k] * s_K2[tid][k];
            bb2 += s_bl[k] * s_br[k];
        }
        d_consts[tid] = r + bb2;
    }
}

// ---------------- A = Wl^T @ Wr  (256x256) --------------------------------
__global__ void matA_kernel(const float* __restrict__ Wl, const float* __restrict__ Wr) {
    __shared__ float col[HH];
    int i = blockIdx.x;   // output row
    int j = threadIdx.x;  // output col
    col[j] = Wl[j * HH + i];
    __syncthreads();
    float acc = 0.f;
    #pragma unroll 8
    for (int k = 0; k < HH; k++) acc = fmaf(col[k], Wr[k * HH + j], acc);
    d_A[i * HH + j] = acc;
}

// ---------------- aux per-node table + zero S -----------------------------
// one warp per node; grid = NN/8 blocks of 256 threads
__global__ void aux_kernel(const float* __restrict__ emb) {
    __shared__ float4 w[5][64];
    __shared__ float  sc[ETN];
    int tid = threadIdx.x;
    if (tid < 64) {
        w[0][tid] = ((const float4*)d_wk2[0])[tid];
        w[1][tid] = ((const float4*)d_wk2[1])[tid];
        w[2][tid] = ((const float4*)d_wk2[2])[tid];
        w[3][tid] = ((const float4*)d_wv)[tid];
        w[4][tid] = ((const float4*)d_wu)[tid];
    }
    if (tid < ETN) sc[tid] = d_consts[tid];
    __syncthreads();

    int warp = tid >> 5, lane = tid & 31;
    int n = blockIdx.x * 8 + warp;   // exact: NN/8 blocks
    const float4* hp = (const float4*)(emb + (size_t)n * HH);
    float4 h0 = hp[lane];
    float4 h1 = hp[32 + lane];

    float acc[5];
    #pragma unroll
    for (int q = 0; q < 5; q++) {
        float4 a = w[q][lane];
        float4 b = w[q][32 + lane];
        acc[q] = h0.x * a.x + h0.y * a.y + h0.z * a.z + h0.w * a.w
               + h1.x * b.x + h1.y * b.y + h1.z * b.z + h1.w * b.w;
    }
    #pragma unroll
    for (int o = 16; o > 0; o >>= 1) {
        #pragma unroll
        for (int q = 0; q < 5; q++) acc[q] += __shfl_xor_sync(0xffffffffu, acc[q], o);
    }
    if (lane == 0) {
        d_aux[n] = make_float4(acc[0] + acc[3] + sc[0],
                               acc[1] + acc[3] + sc[1],
                               acc[2] + acc[3] + sc[2],
                               acc[4]);
        d_S[n] = make_float2(0.f, 0.f);
    }
}

// ---------------- G = h @ A  (64000x256 @ 256x256), pipelined f32x2 SGEMM --
// Double-buffered: Bs filled by cp.async (no regs), As prefetched in regs with
// the transposing STS deferred until after compute. One barrier per k-tile.
#define BM 128
#define BN 128
#define BKk 16
#define SPAD 4

__global__ __launch_bounds__(256, 2)
void gemm_kernel(const float* __restrict__ Hm) {
    __shared__ float As[2][BKk][BM + SPAD];  // transposed h tile
    __shared__ float Bs[2][BKk][BN];
    int bx = blockIdx.x, by = blockIdx.y;
    int tid = threadIdx.x;
    int tx = tid & 15, ty = tid >> 4;

    const float* hBase = Hm + (size_t)bx * BM * HH;
    const float* aBase = d_A + by * BN;

    // acc[m][0..1] -> cols tx*4..+3 ; acc[m][2..3] -> cols 64+tx*4..+3
    u64 acc[8][4];
    #pragma unroll
    for (int m = 0; m < 8; m++)
        #pragma unroll
        for (int j = 0; j < 4; j++) acc[m][j] = 0ULL;

    int lr = tid >> 2;          // 0..63  (h-tile row)
    int lc = (tid & 3) * 4;     // 0,4,8,12 (k offset)
    int ar = tid >> 5;          // 0..7   (A-tile row)
    int ac = (tid & 31) * 4;    // 0..124 (A-tile col)

    uint32_t bs0 = (uint32_t)__cvta_generic_to_shared(&Bs[0][ar][ac]);
    uint32_t bs0b = (uint32_t)__cvta_generic_to_shared(&Bs[0][ar + 8][ac]);
    const uint32_t bufStride = (uint32_t)(sizeof(float) * BKk * BN);

    // ---- prologue: tile 0 ----
    {
        float4 p0 = *(const float4*)(hBase + (size_t)lr * HH + lc);
        float4 p1 = *(const float4*)(hBase + (size_t)(lr + 64) * HH + lc);
        cp_async16(bs0,  aBase + (size_t)ar * HH + ac);
        cp_async16(bs0b, aBase + (size_t)(ar + 8) * HH + ac);
        CP_COMMIT();
        As[0][lc + 0][lr] = p0.x; As[0][lc + 1][lr] = p0.y;
        As[0][lc + 2][lr] = p0.z; As[0][lc + 3][lr] = p0.w;
        As[0][lc + 0][lr + 64] = p1.x; As[0][lc + 1][lr + 64] = p1.y;
        As[0][lc + 2][lr + 64] = p1.z; As[0][lc + 3][lr + 64] = p1.w;
        CP_WAIT0();
        __syncthreads();
    }

    for (int k0 = 0; k0 < HH; k0 += BKk) {
        int cb = (k0 >> 4) & 1, nb = cb ^ 1;
        bool more = (k0 + BKk) < HH;
        float4 n0, n1;
        if (more) {
            int kn = k0 + BKk;
            n0 = *(const float4*)(hBase + (size_t)lr * HH + kn + lc);
            n1 = *(const float4*)(hBase + (size_t)(lr + 64) * HH + kn + lc);
            cp_async16(bs0 + nb * bufStride,  aBase + (size_t)(kn + ar) * HH + ac);
            cp_async16(bs0b + nb * bufStride, aBase + (size_t)(kn + ar + 8) * HH + ac);
            CP_COMMIT();
        }

        #pragma unroll
        for (int kk = 0; kk < BKk; kk++) {
            float4 a0 = *(const float4*)&As[cb][kk][ty * 8];
            float4 a1 = *(const float4*)&As[cb][kk][ty * 8 + 4];
            ulonglong2 bp0 = *(const ulonglong2*)&Bs[cb][kk][tx * 4];
            ulonglong2 bp1 = *(const ulonglong2*)&Bs[cb][kk][64 + tx * 4];
            u64 b[4] = {bp0.x, bp0.y, bp1.x, bp1.y};
            float a[8] = {a0.x, a0.y, a0.z, a0.w, a1.x, a1.y, a1.z, a1.w};
            #pragma unroll
            for (int m = 0; m < 8; m++) {
                u64 ad = pack2(a[m], a[m]);   // broadcast a[m] into both lanes
                #pragma unroll
                for (int j = 0; j < 4; j++) ffma2(acc[m][j], ad, b[j]);
            }
        }

        if (more) {
            As[nb][lc + 0][lr] = n0.x; As[nb][lc + 1][lr] = n0.y;
            As[nb][lc + 2][lr] = n0.z; As[nb][lc + 3][lr] = n0.w;
            As[nb][lc + 0][lr + 64] = n1.x; As[nb][lc + 1][lr + 64] = n1.y;
            As[nb][lc + 2][lr + 64] = n1.z; As[nb][lc + 3][lr + 64] = n1.w;
        }
        CP_WAIT0();
        __syncthreads();
    }

    float* gp = d_G + (size_t)(bx * BM + ty * 8) * HH + by * BN;
    #pragma unroll
    for (int m = 0; m < 8; m++) {
        float4 o0, o1;
        unpack2(acc[m][0], o0.x, o0.y);
        unpack2(acc[m][1], o0.z, o0.w);
        unpack2(acc[m][2], o1.x, o1.y);
        unpack2(acc[m][3], o1.z, o1.w);
        *(float4*)(gp + (size_t)m * HH + tx * 4)      = o0;
        *(float4*)(gp + (size_t)m * HH + 64 + tx * 4) = o1;
    }
}

// ---------------- edge pass: alpha -> exp -> atomic segment sums ----------
// one warp per edge; grid = EE/8 blocks of 256 threads
__global__ void edge_kernel(const float* __restrict__ emb, const float* __restrict__ scores,
                            const int* __restrict__ src, const int* __restrict__ dst,
                            const int* __restrict__ et) {
    int gw = blockIdx.x * 8 + (threadIdx.x >> 5);
    int lane = threadIdx.x & 31;
    int s = __ldg(src + gw);
    int d = __ldg(dst + gw);
    int t = __ldg(et + gw);

    const float4* gq = (const float4*)(d_G + (size_t)d * HH);
    const float4* hs = (const float4*)(emb + (size_t)s * HH);
    float4 a0 = gq[lane], a1 = gq[32 + lane];
    float4 b0 = hs[lane], b1 = hs[32 + lane];
    float acc = a0.x * b0.x + a0.y * b0.y + a0.z * b0.z + a0.w * b0.w
              + a1.x * b1.x + a1.y * b1.y + a1.z * b1.z + a1.w * b1.w;
    #pragma unroll
    for (int o = 16; o > 0; o >>= 1) acc += __shfl_xor_sync(0xffffffffu, acc, o);

    if (lane == 0) {
        float4 ad = d_aux[d];
        float pv = (t == 0) ? ad.x : ((t == 1) ? ad.y : ad.z);
        float u  = d_aux[s].w;
        float alpha = (acc + pv + u) * 0.0625f;  // / sqrt(256)
        float ex = expf(alpha);
        atomicAdd(&d_S[d].x, ex);
        atomicAdd(&d_S[d].y, __ldg(scores + s) * ex);
    }
}

// ---------------- per-graph logits + log-softmax + CE ---------------------
__global__ void logits_kernel(const int* __restrict__ cand, const int* __restrict__ label,
                              float* __restrict__ outLogits) {
    __shared__ float sl[CC];
    __shared__ float red[128];
    int b = blockIdx.x, tid = threadIdx.x;

    float logit = 0.f;
    if (tid < CC) {
        int node = cand[b * CC + tid];
        float2 s = d_S[node];
        logit = (s.x > 0.f) ? (s.y / s.x) : 0.f;
        sl[tid] = logit;
        outLogits[b * CC + tid] = logit;
    }
    red[tid] = (tid < CC) ? logit : -3.4e38f;
    __syncthreads();
    for (int st = 64; st > 0; st >>= 1) {
        if (tid < st) red[tid] = fmaxf(red[tid], red[tid + st]);
        __syncthreads();
    }
    float mx = red[0];
    __syncthreads();
    red[tid] = (tid < CC) ? expf(logit - mx) : 0.f;
    __syncthreads();
    for (int st = 64; st > 0; st >>= 1) {
        if (tid < st) red[tid] += red[tid + st];
        __syncthreads();
    }
    if (tid == 0) {
        int lab = label[b];
        d_lossPart[b] = -(sl[lab] - mx - logf(red[0]));
    }
}

__global__ void loss_kernel(float* __restrict__ outLoss) {
    float v = d_lossPart[threadIdx.x];  // 32 threads == BB
    #pragma unroll
    for (int o = 16; o > 0; o >>= 1) v += __shfl_xor_sync(0xffffffffu, v, o);
    if (threadIdx.x == 0) outLoss[0] = v;
}

// ---------------- launch --------------------------------------------------
extern "C" void kernel_launch(void* const* d_in, const int* in_sizes, int n_in,
                              void* d_out, int out_size) {
    const float* emb    = (const float*)d_in[0];
    const float* scores = (const float*)d_in[1];
    const float* Wl     = (const float*)d_in[2];
    const float* bl     = (const float*)d_in[3];
    const float* Wr     = (const float*)d_in[4];
    const float* br     = (const float*)d_in[5];
    const float* We     = (const float*)d_in[6];
    const float* be     = (const float*)d_in[7];
    const float* eemb   = (const float*)d_in[8];
    const int*   src    = (const int*)d_in[9];
    const int*   dst    = (const int*)d_in[10];
    const int*   et     = (const int*)d_in[11];
    const int*   cand   = (const int*)d_in[12];
    const int*   label  = (const int*)d_in[13];

    float* out = (float*)d_out;
    float* lossPtr;
    float* logitsPtr;
    if (out_size >= BB * CC + 1) {            // [loss, logits...] (tuple order)
        lossPtr = out;
        logitsPtr = out + 1;
    } else if (out_size == BB * CC) {         // logits only
        lossPtr = nullptr;
        logitsPtr = out;
    } else {                                  // loss only
        lossPtr = out;
        void* p = nullptr;
        cudaGetSymbolAddress(&p, d_logitsScratch);
        logitsPtr = (float*)p;
    }

    prep_kernel<<<1, HH>>>(Wl, bl, Wr, br, We, be, eemb);
    matA_kernel<<<HH, HH>>>(Wl, Wr);
    aux_kernel<<<NN / 8, 256>>>(emb);
    gemm_kernel<<<dim3(NN / BM, HH / BN), 256>>>(emb);
    edge_kernel<<<EE / 8, 256>>>(emb, scores, src, dst, et);
    logits_kernel<<<BB, 128>>>(cand, label, logitsPtr);
    if (lossPtr) loss_kernel<<<1, 32>>>(lossPtr);
}

// round 13
// speedup vs baseline: 1.3965x; 1.1281x over previous
#include <cuda_runtime.h>
#include <cuda_bf16.h>
#include <math.h>
#include <stdint.h>

// Problem constants
#define BB     32
#define N_PER_ 2000
#define E_PER_ 16000
#define HH     256
#define EFD    20
#define ETN    3
#define CC     100
#define NN     (BB * N_PER_)     // 64000
#define EE     (BB * E_PER_)     // 512000

typedef unsigned long long u64;

// ---------------- cp.async helpers ----------------------------------------
__device__ __forceinline__ void cp_async16(uint32_t smem_addr, const void* gptr) {
    asm volatile("cp.async.cg.shared.global [%0], [%1], 16;"
                 :: "r"(smem_addr), "l"(gptr));
}
#define CP_COMMIT() asm volatile("cp.async.commit_group;" ::: "memory")
#define CP_WAIT0()  asm volatile("cp.async.wait_group 0;" ::: "memory")

__device__ __forceinline__ uint32_t smem_u32(const void* p) {
    uint32_t a;
    asm("{ .reg .u64 t; cvta.to.shared.u64 t, %1; cvt.u32.u64 %0, t; }"
        : "=r"(a) : "l"(p));
    return a;
}

// ---------------- warp MMA helpers (sm_80+ baseline PTX) -------------------
__device__ __forceinline__ void mma16816(float* d, const uint32_t* a, const uint32_t* b) {
    asm volatile(
        "mma.sync.aligned.m16n8k16.row.col.f32.bf16.bf16.f32 "
        "{%0,%1,%2,%3}, {%4,%5,%6,%7}, {%8,%9}, {%0,%1,%2,%3};"
        : "+f"(d[0]), "+f"(d[1]), "+f"(d[2]), "+f"(d[3])
        : "r"(a[0]), "r"(a[1]), "r"(a[2]), "r"(a[3]), "r"(b[0]), "r"(b[1]));
}
__device__ __forceinline__ void ldsm4(uint32_t* r, uint32_t addr) {
    asm volatile("ldmatrix.sync.aligned.m8n8.x4.shared.b16 {%0,%1,%2,%3}, [%4];"
        : "=r"(r[0]), "=r"(r[1]), "=r"(r[2]), "=r"(r[3]) : "r"(addr));
}
__device__ __forceinline__ void ldsm2(uint32_t* r, uint32_t addr) {
    asm volatile("ldmatrix.sync.aligned.m8n8.x2.shared.b16 {%0,%1}, [%2];"
        : "=r"(r[0]), "=r"(r[1]) : "r"(addr));
}

// ---------------- scratch (static device globals; no runtime alloc) -------
__device__ float          d_G[(size_t)NN * HH];  // h @ A   (65.5 MB)
__device__ __nv_bfloat16  d_Bh[HH * HH];         // split(A^T) hi  [n][k]
__device__ __nv_bfloat16  d_Bl[HH * HH];         // split(A^T) lo  [n][k]
__device__ float  d_wk2[ETN][HH];          // Wl^T K2_t
__device__ float  d_wu[HH];                // Wr^T bl
__device__ float  d_wv[HH];                // Wl^T br
__device__ float  d_consts[ETN];           // bl.K2_t + bl.br
__device__ float4 d_aux[NN];               // (p0+v+c0, p1+v+c1, p2+v+c2, u)
__device__ float2 d_S[NN];                 // (sum exp, sum scores*exp)
__device__ float  d_lossPart[BB];
__device__ float  d_logitsScratch[BB * CC];

// ---------------- prep: gelu(edge_emb), K2 table, folded bias vectors -----
__global__ void prep_kernel(const float* __restrict__ Wl, const float* __restrict__ bl,
                            const float* __restrict__ Wr, const float* __restrict__ br,
                            const float* __restrict__ We, const float* __restrict__ be,
                            const float* __restrict__ eemb) {
    __shared__ float s_ef[ETN][EFD];
    __shared__ float s_K2[ETN][HH];
    __shared__ float s_bl[HH], s_br[HH];
    int tid = threadIdx.x;  // 256 threads

    if (tid < ETN * EFD) {
        float x = eemb[tid];
        s_ef[tid / EFD][tid % EFD] = 0.5f * x * (1.0f + erff(x * 0.70710678118654752f));
    }
    s_bl[tid] = bl[tid];
    s_br[tid] = br[tid];
    __syncthreads();

    float bei = be[tid];
    #pragma unroll
    for (int t = 0; t < ETN; t++) {
        float a = bei;
        #pragma unroll
        for (int j = 0; j < EFD; j++) a += We[tid * EFD + j] * s_ef[t][j];
        s_K2[t][tid] = a;
    }
    __syncthreads();

    float p0 = 0.f, p1 = 0.f, p2 = 0.f, v = 0.f, u = 0.f;
    for (int k = 0; k < HH; k++) {
        float wl = Wl[k * HH + tid];
        float wr = Wr[k * HH + tid];
        p0 += wl * s_K2[0][k];
        p1 += wl * s_K2[1][k];
        p2 += wl * s_K2[2][k];
        v  += wl * s_br[k];
        u  += wr * s_bl[k];
    }
    d_wk2[0][tid] = p0;
    d_wk2[1][tid] = p1;
    d_wk2[2][tid] = p2;
    d_wv[tid] = v;
    d_wu[tid] = u;

    if (tid < ETN) {
        float r = 0.f, bb2 = 0.f;
        for (int k = 0; k < HH; k++) {
            r   += s_bl[k] * s_K2[tid][k];
            bb2 += s_bl[k] * s_br[k];
        }
        d_consts[tid] = r + bb2;
    }
}

// ---------------- A = Wl^T @ Wr, emitted as bf16-split B^T ops ------------
// MMA wants B[n][k] = A[k][n]; write the transposed split directly.
__global__ void matA_kernel(const float* __restrict__ Wl, const float* __restrict__ Wr) {
    __shared__ float col[HH];
    int i = blockIdx.x;   // k index (A row)
    int j = threadIdx.x;  // n index (A col)
    col[j] = Wl[j * HH + i];
    __syncthreads();
    float acc = 0.f;
    #pragma unroll 8
    for (int k = 0; k < HH; k++) acc = fmaf(col[k], Wr[k * HH + j], acc);
    __nv_bfloat16 h = __float2bfloat16(acc);
    d_Bh[j * HH + i] = h;
    d_Bl[j * HH + i] = __float2bfloat16(acc - __bfloat162float(h));
}

// ---------------- aux per-node table + zero S -----------------------------
__global__ void aux_kernel(const float* __restrict__ emb) {
    __shared__ float4 w[5][64];
    __shared__ float  sc[ETN];
    int tid = threadIdx.x;
    if (tid < 64) {
        w[0][tid] = ((const float4*)d_wk2[0])[tid];
        w[1][tid] = ((const float4*)d_wk2[1])[tid];
        w[2][tid] = ((const float4*)d_wk2[2])[tid];
        w[3][tid] = ((const float4*)d_wv)[tid];
        w[4][tid] = ((const float4*)d_wu)[tid];
    }
    if (tid < ETN) sc[tid] = d_consts[tid];
    __syncthreads();

    int warp = tid >> 5, lane = tid & 31;
    int n = blockIdx.x * 8 + warp;
    const float4* hp = (const float4*)(emb + (size_t)n * HH);
    float4 h0 = hp[lane];
    float4 h1 = hp[32 + lane];

    float acc[5];
    #pragma unroll
    for (int q = 0; q < 5; q++) {
        float4 a = w[q][lane];
        float4 b = w[q][32 + lane];
        acc[q] = h0.x * a.x + h0.y * a.y + h0.z * a.z + h0.w * a.w
               + h1.x * b.x + h1.y * b.y + h1.z * b.z + h1.w * b.w;
    }
    #pragma unroll
    for (int o = 16; o > 0; o >>= 1) {
        #pragma unroll
        for (int q = 0; q < 5; q++) acc[q] += __shfl_xor_sync(0xffffffffu, acc[q], o);
    }
    if (lane == 0) {
        d_aux[n] = make_float4(acc[0] + acc[3] + sc[0],
                               acc[1] + acc[3] + sc[1],
                               acc[2] + acc[3] + sc[2],
                               acc[4]);
        d_S[n] = make_float2(0.f, 0.f);
    }
}

// ---------------- G = h @ A via bf16 3-split mma.sync ----------------------
// CTA: M=128, N=256, K in 8 chunks of 32. 512 threads, 16 warps (warp 32x64).
// smem rows padded to 80B => conflict-free ldmatrix. Double-buffered.
#define KC      32
#define ASTR    80
#define A_BYTES (128 * ASTR)      // 10240 per split
#define B_BYTES (256 * ASTR)      // 20480 per split
#define OFF_AH  0
#define OFF_AL  A_BYTES
#define OFF_BH  (2 * A_BYTES)
#define OFF_BL  (2 * A_BYTES + B_BYTES)
#define BUF_SZ  (2 * A_BYTES + 2 * B_BYTES)   // 61440
#define S_TOTAL (2 * BUF_SZ)                  // 122880

__device__ __forceinline__ uint32_t bfhi2(float x0, float x1, float& r0, float& r1) {
    __nv_bfloat16 b0 = __float2bfloat16(x0), b1 = __float2bfloat16(x1);
    r0 = x0 - __bfloat162float(b0);
    r1 = x1 - __bfloat162float(b1);
    return ((uint32_t)__bfloat16_as_ushort(b1) << 16) | (uint32_t)__bfloat16_as_ushort(b0);
}
__device__ __forceinline__ uint32_t bflo2(float x0, float x1) {
    __nv_bfloat16 b0 = __float2bfloat16(x0), b1 = __float2bfloat16(x1);
    return ((uint32_t)__bfloat16_as_ushort(b1) << 16) | (uint32_t)__bfloat16_as_ushort(b0);
}

__global__ __launch_bounds__(512, 1)
void gemm_mma_kernel(const float* __restrict__ Hm) {
    extern __shared__ char smem[];
    uint32_t sb = smem_u32(smem);
    int tid = threadIdx.x, wid = tid >> 5, lane = tid & 31;
    int warpM = wid & 3, warpN = wid >> 2;

    // fill-role indices
    int ar = tid >> 2, aq = tid & 3;       // A: row (0..127), 16B quarter (0..3)
    int bn = tid >> 1, bhf = tid & 1;      // B: n row (0..255), 32B half (0..1)
    const float* aSrc = Hm + (size_t)(blockIdx.x * 128 + ar) * HH + aq * 8;
    const __nv_bfloat16* bhSrc = d_Bh + bn * HH + bhf * 16;
    const __nv_bfloat16* blSrc = d_Bl + bn * HH + bhf * 16;
    uint32_t aDst = (uint32_t)ar * ASTR + (uint32_t)aq * 16;
    uint32_t bDst = (uint32_t)bn * ASTR + (uint32_t)bhf * 32;

    float acc[2][8][4];
    #pragma unroll
    for (int m = 0; m < 2; m++)
        #pragma unroll
        for (int n = 0; n < 8; n++)
            #pragma unroll
            for (int j = 0; j < 4; j++) acc[m][n][j] = 0.f;

    // ldmatrix base offsets (within a buffer)
    uint32_t aRow = (uint32_t)(warpM * 32 + (lane & 15)) * ASTR + ((lane >> 4) * 8) * 2;
    uint32_t bRow = (uint32_t)(warpN * 64 + (lane & 7)) * ASTR + (((lane >> 3) & 1) * 8) * 2;

    // ---- prologue: chunk 0 ----
    {
        cp_async16(sb + OFF_BH + bDst,      bhSrc);
        cp_async16(sb + OFF_BH + bDst + 16, bhSrc + 8);
        cp_async16(sb + OFF_BL + bDst,      blSrc);
        cp_async16(sb + OFF_BL + bDst + 16, blSrc + 8);
        CP_COMMIT();
        float4 f0 = *(const float4*)aSrc;
        float4 f1 = *(const float4*)(aSrc + 4);
        float r0, r1, r2, r3, r4, r5, r6, r7;
        uint4 hi, lo;
        hi.x = bfhi2(f0.x, f0.y, r0, r1);
        hi.y = bfhi2(f0.z, f0.w, r2, r3);
        hi.z = bfhi2(f1.x, f1.y, r4, r5);
        hi.w = bfhi2(f1.z, f1.w, r6, r7);
        lo.x = bflo2(r0, r1); lo.y = bflo2(r2, r3);
        lo.z = bflo2(r4, r5); lo.w = bflo2(r6, r7);
        *(uint4*)(smem + OFF_AH + aDst) = hi;
        *(uint4*)(smem + OFF_AL + aDst) = lo;
        CP_WAIT0();
        __syncthreads();
    }

    for (int c = 0; c < 8; c++) {
        uint32_t cur = (c & 1) * BUF_SZ, nxt = ((c + 1) & 1) * BUF_SZ;
        bool more = c < 7;
        float4 f0, f1;
        if (more) {
            int kn = (c + 1) * KC;
            cp_async16(sb + nxt + OFF_BH + bDst,      bhSrc + kn);
            cp_async16(sb + nxt + OFF_BH + bDst + 16, bhSrc + kn + 8);
            cp_async16(sb + nxt + OFF_BL + bDst,      blSrc + kn);
            cp_async16(sb + nxt + OFF_BL + bDst + 16, blSrc + kn + 8);
            CP_COMMIT();
            f0 = *(const float4*)(aSrc + kn);
            f1 = *(const float4*)(aSrc + kn + 4);
        }

        #pragma unroll
        for (int k16 = 0; k16 < 2; k16++) {
            uint32_t ka = cur + aRow + k16 * 32;   // +16 bf16 = 32B
            uint32_t kb = cur + bRow + k16 * 32;
            uint32_t ah[2][4], al[2][4];
            ldsm4(ah[0], sb + OFF_AH + ka);
            ldsm4(ah[1], sb + OFF_AH + ka + 16 * ASTR);
            ldsm4(al[0], sb + OFF_AL + ka);
            ldsm4(al[1], sb + OFF_AL + ka + 16 * ASTR);
            #pragma unroll
            for (int nt = 0; nt < 8; nt++) {
                uint32_t bh[2], bl[2];
                ldsm2(bh, sb + OFF_BH + kb + nt * 8 * ASTR);
                ldsm2(bl, sb + OFF_BL + kb + nt * 8 * ASTR);
                #pragma unroll
                for (int mt = 0; mt < 2; mt++) {
                    mma16816(acc[mt][nt], ah[mt], bh);
                    mma16816(acc[mt][nt], ah[mt], bl);
                    mma16816(acc[mt][nt], al[mt], bh);
                }
            }
        }

        if (more) {
            float r0, r1, r2, r3, r4, r5, r6, r7;
            uint4 hi, lo;
            hi.x = bfhi2(f0.x, f0.y, r0, r1);
            hi.y = bfhi2(f0.z, f0.w, r2, r3);
            hi.z = bfhi2(f1.x, f1.y, r4, r5);
            hi.w = bfhi2(f1.z, f1.w, r6, r7);
            lo.x = bflo2(r0, r1); lo.y = bflo2(r2, r3);
            lo.z = bflo2(r4, r5); lo.w = bflo2(r6, r7);
            *(uint4*)(smem + nxt + OFF_AH + aDst) = hi;
            *(uint4*)(smem + nxt + OFF_AL + aDst) = lo;
        }
        CP_WAIT0();
        __syncthreads();
    }

    // ---- epilogue: fragments -> d_G ----
    int rbase = blockIdx.x * 128 + warpM * 32 + (lane >> 2);
    int cbase = warpN * 64 + (lane & 3) * 2;
    #pragma unroll
    for (int mt = 0; mt < 2; mt++) {
        #pragma unroll
        for (int nt = 0; nt < 8; nt++) {
            float* g0 = d_G + (size_t)(rbase + mt * 16) * HH + cbase + nt * 8;
            float* g1 = g0 + 8 * HH;
            *(float2*)g0 = make_float2(acc[mt][nt][0], acc[mt][nt][1]);
            *(float2*)g1 = make_float2(acc[mt][nt][2], acc[mt][nt][3]);
        }
    }
}

// ---------------- edge pass: alpha -> exp -> atomic segment sums ----------
__global__ void edge_kernel(const float* __restrict__ emb, const float* __restrict__ scores,
                            const int* __restrict__ src, const int* __restrict__ dst,
                            const int* __restrict__ et) {
    int gw = blockIdx.x * 8 + (threadIdx.x >> 5);
    int lane = threadIdx.x & 31;
    int s = __ldg(src + gw);
    int d = __ldg(dst + gw);
    int t = __ldg(et + gw);

    const float4* gq = (const float4*)(d_G + (size_t)d * HH);
    const float4* hs = (const float4*)(emb + (size_t)s * HH);
    float4 a0 = gq[lane], a1 = gq[32 + lane];
    float4 b0 = hs[lane], b1 = hs[32 + lane];
    float acc = a0.x * b0.x + a0.y * b0.y + a0.z * b0.z + a0.w * b0.w
              + a1.x * b1.x + a1.y * b1.y + a1.z * b1.z + a1.w * b1.w;
    #pragma unroll
    for (int o = 16; o > 0; o >>= 1) acc += __shfl_xor_sync(0xffffffffu, acc, o);

    if (lane == 0) {
        float4 ad = d_aux[d];
        float pv = (t == 0) ? ad.x : ((t == 1) ? ad.y : ad.z);
        float u  = d_aux[s].w;
        float alpha = (acc + pv + u) * 0.0625f;  // / sqrt(256)
        float ex = expf(alpha);
        atomicAdd(&d_S[d].x, ex);
        atomicAdd(&d_S[d].y, __ldg(scores + s) * ex);
    }
}

// ---------------- per-graph logits + log-softmax + CE ---------------------
__global__ void logits_kernel(const int* __restrict__ cand, const int* __restrict__ label,
                              float* __restrict__ outLogits) {
    __shared__ float sl[CC];
    __shared__ float red[128];
    int b = blockIdx.x, tid = threadIdx.x;

    float logit = 0.f;
    if (tid < CC) {
        int node = cand[b * CC + tid];
        float2 s = d_S[node];
        logit = (s.x > 0.f) ? (s.y / s.x) : 0.f;
        sl[tid] = logit;
        outLogits[b * CC + tid] = logit;
    }
    red[tid] = (tid < CC) ? logit : -3.4e38f;
    __syncthreads();
    for (int st = 64; st > 0; st >>= 1) {
        if (tid < st) red[tid] = fmaxf(red[tid], red[tid + st]);
        __syncthreads();
    }
    float mx = red[0];
    __syncthreads();
    red[tid] = (tid < CC) ? expf(logit - mx) : 0.f;
    __syncthreads();
    for (int st = 64; st > 0; st >>= 1) {
        if (tid < st) red[tid] += red[tid + st];
        __syncthreads();
    }
    if (tid == 0) {
        int lab = label[b];
        d_lossPart[b] = -(sl[lab] - mx - logf(red[0]));
    }
}

__global__ void loss_kernel(float* __restrict__ outLoss) {
    float v = d_lossPart[threadIdx.x];  // 32 threads == BB
    #pragma unroll
    for (int o = 16; o > 0; o >>= 1) v += __shfl_xor_sync(0xffffffffu, v, o);
    if (threadIdx.x == 0) outLoss[0] = v;
}

// ---------------- launch --------------------------------------------------
extern "C" void kernel_launch(void* const* d_in, const int* in_sizes, int n_in,
                              void* d_out, int out_size) {
    const float* emb    = (const float*)d_in[0];
    const float* scores = (const float*)d_in[1];
    const float* Wl     = (const float*)d_in[2];
    const float* bl     = (const float*)d_in[3];
    const float* Wr     = (const float*)d_in[4];
    const float* br     = (const float*)d_in[5];
    const float* We     = (const float*)d_in[6];
    const float* be     = (const float*)d_in[7];
    const float* eemb   = (const float*)d_in[8];
    const int*   src    = (const int*)d_in[9];
    const int*   dst    = (const int*)d_in[10];
    const int*   et     = (const int*)d_in[11];
    const int*   cand   = (const int*)d_in[12];
    const int*   label  = (const int*)d_in[13];

    float* out = (float*)d_out;
    float* lossPtr;
    float* logitsPtr;
    if (out_size >= BB * CC + 1) {            // [loss, logits...] (tuple order)
        lossPtr = out;
        logitsPtr = out + 1;
    } else if (out_size == BB * CC) {         // logits only
        lossPtr = nullptr;
        logitsPtr = out;
    } else {                                  // loss only
        lossPtr = out;
        void* p = nullptr;
        cudaGetSymbolAddress(&p, d_logitsScratch);
        logitsPtr = (float*)p;
    }

    cudaFuncSetAttribute(gemm_mma_kernel,
                         cudaFuncAttributeMaxDynamicSharedMemorySize, S_TOTAL);

    prep_kernel<<<1, HH>>>(Wl, bl, Wr, br, We, be, eemb);
    matA_kernel<<<HH, HH>>>(Wl, Wr);
    aux_kernel<<<NN / 8, 256>>>(emb);
    gemm_mma_kernel<<<NN / 128, 512, S_TOTAL>>>(emb);
    edge_kernel<<<EE / 8, 256>>>(emb, scores, src, dst, et);
    logits_kernel<<<BB, 128>>>(cand, label, logitsPtr);
    if (lossPtr) loss_kernel<<<1, 32>>>(lossPtr);
}

// round 14
// speedup vs baseline: 1.4828x; 1.0618x over previous
#include <cuda_runtime.h>
#include <cuda_bf16.h>
#include <math.h>
#include <stdint.h>

// Problem constants
#define BB     32
#define N_PER_ 2000
#define E_PER_ 16000
#define HH     256
#define EFD    20
#define ETN    3
#define CC     100
#define NN     (BB * N_PER_)     // 64000
#define EE     (BB * E_PER_)     // 512000

typedef unsigned long long u64;

// ---------------- cp.async helpers ----------------------------------------
__device__ __forceinline__ void cp_async16(uint32_t smem_addr, const void* gptr) {
    asm volatile("cp.async.cg.shared.global [%0], [%1], 16;"
                 :: "r"(smem_addr), "l"(gptr));
}
#define CP_COMMIT() asm volatile("cp.async.commit_group;" ::: "memory")
#define CP_WAIT1()  asm volatile("cp.async.wait_group 1;" ::: "memory")

__device__ __forceinline__ uint32_t smem_u32(const void* p) {
    uint32_t a;
    asm("{ .reg .u64 t; cvta.to.shared.u64 t, %1; cvt.u32.u64 %0, t; }"
        : "=r"(a) : "l"(p));
    return a;
}

// ---------------- warp MMA helpers (sm_80+ baseline PTX) -------------------
__device__ __forceinline__ void mma16816(float* d, const uint32_t* a, const uint32_t* b) {
    asm volatile(
        "mma.sync.aligned.m16n8k16.row.col.f32.bf16.bf16.f32 "
        "{%0,%1,%2,%3}, {%4,%5,%6,%7}, {%8,%9}, {%0,%1,%2,%3};"
        : "+f"(d[0]), "+f"(d[1]), "+f"(d[2]), "+f"(d[3])
        : "r"(a[0]), "r"(a[1]), "r"(a[2]), "r"(a[3]), "r"(b[0]), "r"(b[1]));
}
__device__ __forceinline__ void ldsm4(uint32_t* r, uint32_t addr) {
    asm volatile("ldmatrix.sync.aligned.m8n8.x4.shared.b16 {%0,%1,%2,%3}, [%4];"
        : "=r"(r[0]), "=r"(r[1]), "=r"(r[2]), "=r"(r[3]) : "r"(addr));
}
__device__ __forceinline__ void ldsm2(uint32_t* r, uint32_t addr) {
    asm volatile("ldmatrix.sync.aligned.m8n8.x2.shared.b16 {%0,%1}, [%2];"
        : "=r"(r[0]), "=r"(r[1]) : "r"(addr));
}

// ---------------- bf16 split helpers ---------------------------------------
__device__ __forceinline__ uint32_t bfhi2(float x0, float x1, float& r0, float& r1) {
    __nv_bfloat16 b0 = __float2bfloat16(x0), b1 = __float2bfloat16(x1);
    r0 = x0 - __bfloat162float(b0);
    r1 = x1 - __bfloat162float(b1);
    return ((uint32_t)__bfloat16_as_ushort(b1) << 16) | (uint32_t)__bfloat16_as_ushort(b0);
}
__device__ __forceinline__ uint32_t bflo2(float x0, float x1) {
    __nv_bfloat16 b0 = __float2bfloat16(x0), b1 = __float2bfloat16(x1);
    return ((uint32_t)__bfloat16_as_ushort(b1) << 16) | (uint32_t)__bfloat16_as_ushort(b0);
}

// ---------------- scratch (static device globals; no runtime alloc) -------
__device__ float          d_G[(size_t)NN * HH];       // h @ A   (65.5 MB)
__device__ __nv_bfloat16  d_Hh[(size_t)NN * HH];      // split(h) hi (32 MB)
__device__ __nv_bfloat16  d_Hl[(size_t)NN * HH];      // split(h) lo (32 MB)
__device__ __nv_bfloat16  d_Bh[HH * HH];              // split(A^T) hi [n][k]
__device__ __nv_bfloat16  d_Bl[HH * HH];              // split(A^T) lo [n][k]
__device__ float  d_wk2[ETN][HH];          // Wl^T K2_t
__device__ float  d_wu[HH];                // Wr^T bl
__device__ float  d_wv[HH];                // Wl^T br
__device__ float  d_consts[ETN];           // bl.K2_t + bl.br
__device__ float4 d_aux[NN];               // (p0+v+c0, p1+v+c1, p2+v+c2, u)
__device__ float2 d_S[NN];                 // (sum exp, sum scores*exp)
__device__ float  d_lossPart[BB];
__device__ float  d_logitsScratch[BB * CC];

// ---------------- prep: gelu(edge_emb), K2 table, folded bias vectors -----
__global__ void prep_kernel(const float* __restrict__ Wl, const float* __restrict__ bl,
                            const float* __restrict__ Wr, const float* __restrict__ br,
                            const float* __restrict__ We, const float* __restrict__ be,
                            const float* __restrict__ eemb) {
    __shared__ float s_ef[ETN][EFD];
    __shared__ float s_K2[ETN][HH];
    __shared__ float s_bl[HH], s_br[HH];
    int tid = threadIdx.x;  // 256 threads

    if (tid < ETN * EFD) {
        float x = eemb[tid];
        s_ef[tid / EFD][tid % EFD] = 0.5f * x * (1.0f + erff(x * 0.70710678118654752f));
    }
    s_bl[tid] = bl[tid];
    s_br[tid] = br[tid];
    __syncthreads();

    float bei = be[tid];
    #pragma unroll
    for (int t = 0; t < ETN; t++) {
        float a = bei;
        #pragma unroll
        for (int j = 0; j < EFD; j++) a += We[tid * EFD + j] * s_ef[t][j];
        s_K2[t][tid] = a;
    }
    __syncthreads();

    float p0 = 0.f, p1 = 0.f, p2 = 0.f, v = 0.f, u = 0.f;
    for (int k = 0; k < HH; k++) {
        float wl = Wl[k * HH + tid];
        float wr = Wr[k * HH + tid];
        p0 += wl * s_K2[0][k];
        p1 += wl * s_K2[1][k];
        p2 += wl * s_K2[2][k];
        v  += wl * s_br[k];
        u  += wr * s_bl[k];
    }
    d_wk2[0][tid] = p0;
    d_wk2[1][tid] = p1;
    d_wk2[2][tid] = p2;
    d_wv[tid] = v;
    d_wu[tid] = u;

    if (tid < ETN) {
        float r = 0.f, bb2 = 0.f;
        for (int k = 0; k < HH; k++) {
            r   += s_bl[k] * s_K2[tid][k];
            bb2 += s_bl[k] * s_br[k];
        }
        d_consts[tid] = r + bb2;
    }
}

// ---------------- A = Wl^T @ Wr, emitted as bf16-split B^T ops ------------
__global__ void matA_kernel(const float* __restrict__ Wl, const float* __restrict__ Wr) {
    __shared__ float col[HH];
    int i = blockIdx.x;   // k index (A row)
    int j = threadIdx.x;  // n index (A col)
    col[j] = Wl[j * HH + i];
    __syncthreads();
    float acc = 0.f;
    #pragma unroll 8
    for (int k = 0; k < HH; k++) acc = fmaf(col[k], Wr[k * HH + j], acc);
    __nv_bfloat16 h = __float2bfloat16(acc);
    d_Bh[j * HH + i] = h;
    d_Bl[j * HH + i] = __float2bfloat16(acc - __bfloat162float(h));
}

// ---------------- aux per-node table + H bf16 split + zero S --------------
__global__ void aux_kernel(const float* __restrict__ emb) {
    __shared__ float4 w[5][64];
    __shared__ float  sc[ETN];
    int tid = threadIdx.x;
    if (tid < 64) {
        w[0][tid] = ((const float4*)d_wk2[0])[tid];
        w[1][tid] = ((const float4*)d_wk2[1])[tid];
        w[2][tid] = ((const float4*)d_wk2[2])[tid];
        w[3][tid] = ((const float4*)d_wv)[tid];
        w[4][tid] = ((const float4*)d_wu)[tid];
    }
    if (tid < ETN) sc[tid] = d_consts[tid];
    __syncthreads();

    int warp = tid >> 5, lane = tid & 31;
    int n = blockIdx.x * 8 + warp;
    const float4* hp = (const float4*)(emb + (size_t)n * HH);
    float4 h0 = hp[lane];
    float4 h1 = hp[32 + lane];

    // ---- emit bf16 hi/lo split of h (cols 4*lane.. and 128+4*lane..) ----
    {
        float r0, r1, r2, r3;
        uint2 hi0, hi1, lo0, lo1;
        hi0.x = bfhi2(h0.x, h0.y, r0, r1);
        hi0.y = bfhi2(h0.z, h0.w, r2, r3);
        lo0.x = bflo2(r0, r1);
        lo0.y = bflo2(r2, r3);
        hi1.x = bfhi2(h1.x, h1.y, r0, r1);
        hi1.y = bfhi2(h1.z, h1.w, r2, r3);
        lo1.x = bflo2(r0, r1);
        lo1.y = bflo2(r2, r3);
        uint2* hh = (uint2*)(d_Hh + (size_t)n * HH);
        uint2* hl = (uint2*)(d_Hl + (size_t)n * HH);
        hh[lane] = hi0;
        hh[32 + lane] = hi1;
        hl[lane] = lo0;
        hl[32 + lane] = lo1;
    }

    float acc[5];
    #pragma unroll
    for (int q = 0; q < 5; q++) {
        float4 a = w[q][lane];
        float4 b = w[q][32 + lane];
        acc[q] = h0.x * a.x + h0.y * a.y + h0.z * a.z + h0.w * a.w
               + h1.x * b.x + h1.y * b.y + h1.z * b.z + h1.w * b.w;
    }
    #pragma unroll
    for (int o = 16; o > 0; o >>= 1) {
        #pragma unroll
        for (int q = 0; q < 5; q++) acc[q] += __shfl_xor_sync(0xffffffffu, acc[q], o);
    }
    if (lane == 0) {
        d_aux[n] = make_float4(acc[0] + acc[3] + sc[0],
                               acc[1] + acc[3] + sc[1],
                               acc[2] + acc[3] + sc[2],
                               acc[4]);
        d_S[n] = make_float2(0.f, 0.f);
    }
}

// ---------------- G = h @ A via bf16 3-split mma.sync, 3-stage pipeline ----
// CTA: M=128, N=256, K in 8 chunks of 32. 512 threads, 16 warps (warp 32x64).
// All operands pre-split bf16 in gmem -> mainloop is pure cp.async/ldsm/mma.
#define KC      32
#define ASTR    80
#define A_BYTES (128 * ASTR)      // 10240 per split
#define B_BYTES (256 * ASTR)      // 20480 per split
#define OFF_AH  0
#define OFF_AL  A_BYTES
#define OFF_BH  (2 * A_BYTES)
#define OFF_BL  (2 * A_BYTES + B_BYTES)
#define BUF_SZ  (2 * A_BYTES + 2 * B_BYTES)   // 61440
#define NSTAGE  3
#define S_TOTAL (NSTAGE * BUF_SZ)             // 184320

__global__ __launch_bounds__(512, 1)
void gemm_mma_kernel() {
    extern __shared__ char smem[];
    uint32_t sb = smem_u32(smem);
    int tid = threadIdx.x, wid = tid >> 5, lane = tid & 31;
    int warpM = wid & 3, warpN = wid >> 2;

    // fill-role indices: A piece (1 per split), B pieces (2 per split)
    int arow = tid >> 2, aq = tid & 3;
    const __nv_bfloat16* ahSrc = d_Hh + (size_t)(blockIdx.x * 128 + arow) * HH + aq * 8;
    const __nv_bfloat16* alSrc = d_Hl + (size_t)(blockIdx.x * 128 + arow) * HH + aq * 8;
    uint32_t aDst = (uint32_t)arow * ASTR + (uint32_t)aq * 16;

    int b0row = tid >> 2, b0q = tid & 3;            // pieces 0..511
    int b1row = 128 + (tid >> 2), b1q = tid & 3;    // pieces 512..1023
    const __nv_bfloat16* bh0 = d_Bh + b0row * HH + b0q * 8;
    const __nv_bfloat16* bl0 = d_Bl + b0row * HH + b0q * 8;
    const __nv_bfloat16* bh1 = d_Bh + b1row * HH + b1q * 8;
    const __nv_bfloat16* bl1 = d_Bl + b1row * HH + b1q * 8;
    uint32_t bDst0 = (uint32_t)b0row * ASTR + (uint32_t)b0q * 16;
    uint32_t bDst1 = (uint32_t)b1row * ASTR + (uint32_t)b1q * 16;

    float acc[2][8][4];
    #pragma unroll
    for (int m = 0; m < 2; m++)
        #pragma unroll
        for (int n = 0; n < 8; n++)
            #pragma unroll
            for (int j = 0; j < 4; j++) acc[m][n][j] = 0.f;

    uint32_t aRow = (uint32_t)(warpM * 32 + (lane & 15)) * ASTR + ((lane >> 4) * 8) * 2;
    uint32_t bRow = (uint32_t)(warpN * 64 + (lane & 7)) * ASTR + (((lane >> 3) & 1) * 8) * 2;

    // stage issue: 6 cp.async + commit
    auto issue = [&](int c) {
        if (c < 8) {
            uint32_t buf = sb + (uint32_t)(c % NSTAGE) * BUF_SZ;
            int K0 = c * KC;
            cp_async16(buf + OFF_AH + aDst,  ahSrc + K0);
            cp_async16(buf + OFF_AL + aDst,  alSrc + K0);
            cp_async16(buf + OFF_BH + bDst0, bh0 + K0);
            cp_async16(buf + OFF_BL + bDst0, bl0 + K0);
            cp_async16(buf + OFF_BH + bDst1, bh1 + K0);
            cp_async16(buf + OFF_BL + bDst1, bl1 + K0);
        }
        CP_COMMIT();  // commit even if empty: keeps group count in lockstep
    };

    issue(0);
    issue(1);

    for (int c = 0; c < 8; c++) {
        CP_WAIT1();          // stage c complete (<=1 younger group outstanding)
        __syncthreads();     // all threads' pieces visible

        uint32_t cur = (uint32_t)(c % NSTAGE) * BUF_SZ;
        #pragma unroll
        for (int k16 = 0; k16 < 2; k16++) {
            uint32_t ka = cur + aRow + k16 * 32;
            uint32_t kb = cur + bRow + k16 * 32;
            uint32_t ah[2][4], al[2][4];
            ldsm4(ah[0], sb + OFF_AH + ka);
            ldsm4(ah[1], sb + OFF_AH + ka + 16 * ASTR);
            ldsm4(al[0], sb + OFF_AL + ka);
            ldsm4(al[1], sb + OFF_AL + ka + 16 * ASTR);
            #pragma unroll
            for (int nt = 0; nt < 8; nt++) {
                uint32_t bh[2], bl[2];
                ldsm2(bh, sb + OFF_BH + kb + nt * 8 * ASTR);
                ldsm2(bl, sb + OFF_BL + kb + nt * 8 * ASTR);
                #pragma unroll
                for (int mt = 0; mt < 2; mt++) {
                    mma16816(acc[mt][nt], ah[mt], bh);
                    mma16816(acc[mt][nt], ah[mt], bl);
                    mma16816(acc[mt][nt], al[mt], bh);
                }
            }
        }
        __syncthreads();     // all reads of buffer (c%3) done before refill
        issue(c + 2);
    }

    // ---- epilogue: fragments -> d_G ----
    int rbase = blockIdx.x * 128 + warpM * 32 + (lane >> 2);
    int cbase = warpN * 64 + (lane & 3) * 2;
    #pragma unroll
    for (int mt = 0; mt < 2; mt++) {
        #pragma unroll
        for (int nt = 0; nt < 8; nt++) {
            float* g0 = d_G + (size_t)(rbase + mt * 16) * HH + cbase + nt * 8;
            float* g1 = g0 + 8 * HH;
            *(float2*)g0 = make_float2(acc[mt][nt][0], acc[mt][nt][1]);
            *(float2*)g1 = make_float2(acc[mt][nt][2], acc[mt][nt][3]);
        }
    }
}

// ---------------- edge pass: 16 lanes/edge, atomic segment sums -----------
__global__ void edge_kernel(const float* __restrict__ emb, const float* __restrict__ scores,
                            const int* __restrict__ src, const int* __restrict__ dst,
                            const int* __restrict__ et) {
    int eg = blockIdx.x * 16 + (threadIdx.x >> 4);
    int l = threadIdx.x & 15;
    int s = __ldg(src + eg);
    int d = __ldg(dst + eg);
    int t = __ldg(et + eg);

    const float4* gq = (const float4*)(d_G + (size_t)d * HH);
    const float4* hs = (const float4*)(emb + (size_t)s * HH);
    float acc = 0.f;
    #pragma unroll
    for (int j = 0; j < 4; j++) {
        float4 a = gq[j * 16 + l];
        float4 b = hs[j * 16 + l];
        acc += a.x * b.x + a.y * b.y + a.z * b.z + a.w * b.w;
    }
    #pragma unroll
    for (int o = 8; o > 0; o >>= 1) acc += __shfl_xor_sync(0xffffffffu, acc, o);

    if (l == 0) {
        float4 ad = d_aux[d];
        float pv = (t == 0) ? ad.x : ((t == 1) ? ad.y : ad.z);
        float u  = d_aux[s].w;
        float alpha = (acc + pv + u) * 0.0625f;  // / sqrt(256)
        float ex = expf(alpha);
        atomicAdd(&d_S[d].x, ex);
        atomicAdd(&d_S[d].y, __ldg(scores + s) * ex);
    }
}

// ---------------- per-graph logits + log-softmax + CE ---------------------
__global__ void logits_kernel(const int* __restrict__ cand, const int* __restrict__ label,
                              float* __restrict__ outLogits) {
    __shared__ float sl[CC];
    __shared__ float red[128];
    int b = blockIdx.x, tid = threadIdx.x;

    float logit = 0.f;
    if (tid < CC) {
        int node = cand[b * CC + tid];
        float2 s = d_S[node];
        logit = (s.x > 0.f) ? (s.y / s.x) : 0.f;
        sl[tid] = logit;
        outLogits[b * CC + tid] = logit;
    }
    red[tid] = (tid < CC) ? logit : -3.4e38f;
    __syncthreads();
    for (int st = 64; st > 0; st >>= 1) {
        if (tid < st) red[tid] = fmaxf(red[tid], red[tid + st]);
        __syncthreads();
    }
    float mx = red[0];
    __syncthreads();
    red[tid] = (tid < CC) ? expf(logit - mx) : 0.f;
    __syncthreads();
    for (int st = 64; st > 0; st >>= 1) {
        if (tid < st) red[tid] += red[tid + st];
        __syncthreads();
    }
    if (tid == 0) {
        int lab = label[b];
        d_lossPart[b] = -(sl[lab] - mx - logf(red[0]));
    }
}

__global__ void loss_kernel(float* __restrict__ outLoss) {
    float v = d_lossPart[threadIdx.x];  // 32 threads == BB
    #pragma unroll
    for (int o = 16; o > 0; o >>= 1) v += __shfl_xor_sync(0xffffffffu, v, o);
    if (threadIdx.x == 0) outLoss[0] = v;
}

// ---------------- launch --------------------------------------------------
extern "C" void kernel_launch(void* const* d_in, const int* in_sizes, int n_in,
                              void* d_out, int out_size) {
    const float* emb    = (const float*)d_in[0];
    const float* scores = (const float*)d_in[1];
    const float* Wl     = (const float*)d_in[2];
    const float* bl     = (const float*)d_in[3];
    const float* Wr     = (const float*)d_in[4];
    const float* br     = (const float*)d_in[5];
    const float* We     = (const float*)d_in[6];
    const float* be     = (const float*)d_in[7];
    const float* eemb   = (const float*)d_in[8];
    const int*   src    = (const int*)d_in[9];
    const int*   dst    = (const int*)d_in[10];
    const int*   et     = (const int*)d_in[11];
    const int*   cand   = (const int*)d_in[12];
    const int*   label  = (const int*)d_in[13];

    float* out = (float*)d_out;
    float* lossPtr;
    float* logitsPtr;
    if (out_size >= BB * CC + 1) {            // [loss, logits...] (tuple order)
        lossPtr = out;
        logitsPtr = out + 1;
    } else if (out_size == BB * CC) {         // logits only
        lossPtr = nullptr;
        logitsPtr = out;
    } else {                                  // loss only
        lossPtr = out;
        void* p = nullptr;
        cudaGetSymbolAddress(&p, d_logitsScratch);
        logitsPtr = (float*)p;
    }

    cudaFuncSetAttribute(gemm_mma_kernel,
                         cudaFuncAttributeMaxDynamicSharedMemorySize, S_TOTAL);

    prep_kernel<<<1, HH>>>(Wl, bl, Wr, br, We, be, eemb);
    matA_kernel<<<HH, HH>>>(Wl, Wr);
    aux_kernel<<<NN / 8, 256>>>(emb);
    gemm_mma_kernel<<<NN / 128, 512, S_TOTAL>>>();
    edge_kernel<<<EE / 16, 256>>>(emb, scores, src, dst, et);
    logits_kernel<<<BB, 128>>>(cand, label, logitsPtr);
    if (lossPtr) loss_kernel<<<1, 32>>>(lossPtr);
}

// round 15
// speedup vs baseline: 1.5777x; 1.0640x over previous
#include <cuda_runtime.h>
#include <cuda_bf16.h>
#include <math.h>
#include <stdint.h>

// Problem constants
#define BB     32
#define N_PER_ 2000
#define E_PER_ 16000
#define HH     256
#define EFD    20
#define ETN    3
#define CC     100
#define NN     (BB * N_PER_)     // 64000
#define EE     (BB * E_PER_)     // 512000

typedef unsigned long long u64;

// ---------------- cp.async helpers ----------------------------------------
__device__ __forceinline__ void cp_async16(uint32_t smem_addr, const void* gptr) {
    asm volatile("cp.async.cg.shared.global [%0], [%1], 16;"
                 :: "r"(smem_addr), "l"(gptr));
}
#define CP_COMMIT() asm volatile("cp.async.commit_group;" ::: "memory")
#define CP_WAIT1()  asm volatile("cp.async.wait_group 1;" ::: "memory")

__device__ __forceinline__ uint32_t smem_u32(const void* p) {
    uint32_t a;
    asm("{ .reg .u64 t; cvta.to.shared.u64 t, %1; cvt.u32.u64 %0, t; }"
        : "=r"(a) : "l"(p));
    return a;
}

// ---------------- warp MMA helpers (sm_80+ baseline PTX) -------------------
__device__ __forceinline__ void mma16816(float* d, const uint32_t* a, const uint32_t* b) {
    asm volatile(
        "mma.sync.aligned.m16n8k16.row.col.f32.bf16.bf16.f32 "
        "{%0,%1,%2,%3}, {%4,%5,%6,%7}, {%8,%9}, {%0,%1,%2,%3};"
        : "+f"(d[0]), "+f"(d[1]), "+f"(d[2]), "+f"(d[3])
        : "r"(a[0]), "r"(a[1]), "r"(a[2]), "r"(a[3]), "r"(b[0]), "r"(b[1]));
}
__device__ __forceinline__ void ldsm4(uint32_t* r, uint32_t addr) {
    asm volatile("ldmatrix.sync.aligned.m8n8.x4.shared.b16 {%0,%1,%2,%3}, [%4];"
        : "=r"(r[0]), "=r"(r[1]), "=r"(r[2]), "=r"(r[3]) : "r"(addr));
}

// ---------------- bf16 split helpers ---------------------------------------
__device__ __forceinline__ uint32_t bfhi2(float x0, float x1, float& r0, float& r1) {
    __nv_bfloat16 b0 = __float2bfloat16(x0), b1 = __float2bfloat16(x1);
    r0 = x0 - __bfloat162float(b0);
    r1 = x1 - __bfloat162float(b1);
    return ((uint32_t)__bfloat16_as_ushort(b1) << 16) | (uint32_t)__bfloat16_as_ushort(b0);
}
__device__ __forceinline__ uint32_t bflo2(float x0, float x1) {
    __nv_bfloat16 b0 = __float2bfloat16(x0), b1 = __float2bfloat16(x1);
    return ((uint32_t)__bfloat16_as_ushort(b1) << 16) | (uint32_t)__bfloat16_as_ushort(b0);
}

// ---------------- scratch (static device globals; no runtime alloc) -------
__device__ float          d_G[(size_t)NN * HH];       // h @ A   (65.5 MB)
__device__ __nv_bfloat16  d_Hh[(size_t)NN * HH];      // split(h) hi (32 MB)
__device__ __nv_bfloat16  d_Hl[(size_t)NN * HH];      // split(h) lo (32 MB)
__device__ __nv_bfloat16  d_Bh[HH * HH];              // split(A^T) hi [n][k]
__device__ __nv_bfloat16  d_Bl[HH * HH];              // split(A^T) lo [n][k]
__device__ float  d_wk2[ETN][HH];          // Wl^T K2_t
__device__ float  d_wu[HH];                // Wr^T bl
__device__ float  d_wv[HH];                // Wl^T br
__device__ float  d_consts[ETN];           // bl.K2_t + bl.br
__device__ float4 d_aux[NN];               // (p0+v+c0, p1+v+c1, p2+v+c2, u)
__device__ float2 d_S[NN];                 // (sum exp, sum scores*exp)
__device__ float  d_lossPart[BB];
__device__ float  d_logitsScratch[BB * CC];

// ---------------- prep: gelu(edge_emb), K2 table, folded bias vectors -----
__global__ void prep_kernel(const float* __restrict__ Wl, const float* __restrict__ bl,
                            const float* __restrict__ Wr, const float* __restrict__ br,
                            const float* __restrict__ We, const float* __restrict__ be,
                            const float* __restrict__ eemb) {
    __shared__ float s_ef[ETN][EFD];
    __shared__ float s_K2[ETN][HH];
    __shared__ float s_bl[HH], s_br[HH];
    int tid = threadIdx.x;  // 256 threads

    if (tid < ETN * EFD) {
        float x = eemb[tid];
        s_ef[tid / EFD][tid % EFD] = 0.5f * x * (1.0f + erff(x * 0.70710678118654752f));
    }
    s_bl[tid] = bl[tid];
    s_br[tid] = br[tid];
    __syncthreads();

    float bei = be[tid];
    #pragma unroll
    for (int t = 0; t < ETN; t++) {
        float a = bei;
        #pragma unroll
        for (int j = 0; j < EFD; j++) a += We[tid * EFD + j] * s_ef[t][j];
        s_K2[t][tid] = a;
    }
    __syncthreads();

    float p0 = 0.f, p1 = 0.f, p2 = 0.f, v = 0.f, u = 0.f;
    for (int k = 0; k < HH; k++) {
        float wl = Wl[k * HH + tid];
        float wr = Wr[k * HH + tid];
        p0 += wl * s_K2[0][k];
        p1 += wl * s_K2[1][k];
        p2 += wl * s_K2[2][k];
        v  += wl * s_br[k];
        u  += wr * s_bl[k];
    }
    d_wk2[0][tid] = p0;
    d_wk2[1][tid] = p1;
    d_wk2[2][tid] = p2;
    d_wv[tid] = v;
    d_wu[tid] = u;

    if (tid < ETN) {
        float r = 0.f, bb2 = 0.f;
        for (int k = 0; k < HH; k++) {
            r   += s_bl[k] * s_K2[tid][k];
            bb2 += s_bl[k] * s_br[k];
        }
        d_consts[tid] = r + bb2;
    }
}

// ---------------- A = Wl^T @ Wr, emitted as bf16-split B^T ops ------------
__global__ void matA_kernel(const float* __restrict__ Wl, const float* __restrict__ Wr) {
    __shared__ float col[HH];
    int i = blockIdx.x;   // k index (A row)
    int j = threadIdx.x;  // n index (A col)
    col[j] = Wl[j * HH + i];
    __syncthreads();
    float acc = 0.f;
    #pragma unroll 8
    for (int k = 0; k < HH; k++) acc = fmaf(col[k], Wr[k * HH + j], acc);
    __nv_bfloat16 h = __float2bfloat16(acc);
    d_Bh[j * HH + i] = h;
    d_Bl[j * HH + i] = __float2bfloat16(acc - __bfloat162float(h));
}

// ---------------- aux per-node table + H bf16 split + zero S --------------
__global__ void aux_kernel(const float* __restrict__ emb) {
    __shared__ float4 w[5][64];
    __shared__ float  sc[ETN];
    int tid = threadIdx.x;
    if (tid < 64) {
        w[0][tid] = ((const float4*)d_wk2[0])[tid];
        w[1][tid] = ((const float4*)d_wk2[1])[tid];
        w[2][tid] = ((const float4*)d_wk2[2])[tid];
        w[3][tid] = ((const float4*)d_wv)[tid];
        w[4][tid] = ((const float4*)d_wu)[tid];
    }
    if (tid < ETN) sc[tid] = d_consts[tid];
    __syncthreads();

    int warp = tid >> 5, lane = tid & 31;
    int n = blockIdx.x * 8 + warp;
    const float4* hp = (const float4*)(emb + (size_t)n * HH);
    float4 h0 = hp[lane];
    float4 h1 = hp[32 + lane];

    // ---- emit bf16 hi/lo split of h ----
    {
        float r0, r1, r2, r3;
        uint2 hi0, hi1, lo0, lo1;
        hi0.x = bfhi2(h0.x, h0.y, r0, r1);
        hi0.y = bfhi2(h0.z, h0.w, r2, r3);
        lo0.x = bflo2(r0, r1);
        lo0.y = bflo2(r2, r3);
        hi1.x = bfhi2(h1.x, h1.y, r0, r1);
        hi1.y = bfhi2(h1.z, h1.w, r2, r3);
        lo1.x = bflo2(r0, r1);
        lo1.y = bflo2(r2, r3);
        uint2* hh = (uint2*)(d_Hh + (size_t)n * HH);
        uint2* hl = (uint2*)(d_Hl + (size_t)n * HH);
        hh[lane] = hi0;
        hh[32 + lane] = hi1;
        hl[lane] = lo0;
        hl[32 + lane] = lo1;
    }

    float acc[5];
    #pragma unroll
    for (int q = 0; q < 5; q++) {
        float4 a = w[q][lane];
        float4 b = w[q][32 + lane];
        acc[q] = h0.x * a.x + h0.y * a.y + h0.z * a.z + h0.w * a.w
               + h1.x * b.x + h1.y * b.y + h1.z * b.z + h1.w * b.w;
    }
    #pragma unroll
    for (int o = 16; o > 0; o >>= 1) {
        #pragma unroll
        for (int q = 0; q < 5; q++) acc[q] += __shfl_xor_sync(0xffffffffu, acc[q], o);
    }
    if (lane == 0) {
        d_aux[n] = make_float4(acc[0] + acc[3] + sc[0],
                               acc[1] + acc[3] + sc[1],
                               acc[2] + acc[3] + sc[2],
                               acc[4]);
        d_S[n] = make_float2(0.f, 0.f);
    }
}

// ---------------- G = h @ A via bf16 3-split mma.sync, 3-stage pipeline ----
// CTA: M=128, N=256, K in 8 chunks of 32. 512 threads, 16 warps (warp 32x64).
// One barrier per chunk; cp.async for chunk c+2 issued BEFORE compute of c.
// B fragments via ldsm4 (2 n-tiles per instruction).
#define KC      32
#define ASTR    80
#define A_BYTES (128 * ASTR)      // 10240 per split
#define B_BYTES (256 * ASTR)      // 20480 per split
#define OFF_AH  0
#define OFF_AL  A_BYTES
#define OFF_BH  (2 * A_BYTES)
#define OFF_BL  (2 * A_BYTES + B_BYTES)
#define BUF_SZ  (2 * A_BYTES + 2 * B_BYTES)   // 61440
#define NSTAGE  3
#define S_TOTAL (NSTAGE * BUF_SZ)             // 184320

__global__ __launch_bounds__(512, 1)
void gemm_mma_kernel() {
    extern __shared__ char smem[];
    uint32_t sb = smem_u32(smem);
    int tid = threadIdx.x, wid = tid >> 5, lane = tid & 31;
    int warpM = wid & 3, warpN = wid >> 2;

    // fill-role indices
    int arow = tid >> 2, aq = tid & 3;
    const __nv_bfloat16* ahSrc = d_Hh + (size_t)(blockIdx.x * 128 + arow) * HH + aq * 8;
    const __nv_bfloat16* alSrc = d_Hl + (size_t)(blockIdx.x * 128 + arow) * HH + aq * 8;
    uint32_t aDst = (uint32_t)arow * ASTR + (uint32_t)aq * 16;

    int b0row = tid >> 2, b0q = tid & 3;            // pieces 0..511
    int b1row = 128 + (tid >> 2), b1q = tid & 3;    // pieces 512..1023
    const __nv_bfloat16* bh0 = d_Bh + b0row * HH + b0q * 8;
    const __nv_bfloat16* bl0 = d_Bl + b0row * HH + b0q * 8;
    const __nv_bfloat16* bh1 = d_Bh + b1row * HH + b1q * 8;
    const __nv_bfloat16* bl1 = d_Bl + b1row * HH + b1q * 8;
    uint32_t bDst0 = (uint32_t)b0row * ASTR + (uint32_t)b0q * 16;
    uint32_t bDst1 = (uint32_t)b1row * ASTR + (uint32_t)b1q * 16;

    float acc[2][8][4];
    #pragma unroll
    for (int m = 0; m < 2; m++)
        #pragma unroll
        for (int n = 0; n < 8; n++)
            #pragma unroll
            for (int j = 0; j < 4; j++) acc[m][n][j] = 0.f;

    // ldmatrix base offsets (within a buffer)
    uint32_t aRow = (uint32_t)(warpM * 32 + (lane & 15)) * ASTR + ((lane >> 4) * 8) * 2;
    // B x4: matrices {nt_even.k0, nt_even.k1, nt_odd.k0, nt_odd.k1}
    uint32_t bRow4 = (uint32_t)(warpN * 64 + ((lane >> 4) & 1) * 8 + (lane & 7)) * ASTR
                   + (((lane >> 3) & 1) * 8) * 2;

    auto issue = [&](int c) {
        if (c < 8) {
            uint32_t buf = sb + (uint32_t)(c % NSTAGE) * BUF_SZ;
            int K0 = c * KC;
            cp_async16(buf + OFF_AH + aDst,  ahSrc + K0);
            cp_async16(buf + OFF_AL + aDst,  alSrc + K0);
            cp_async16(buf + OFF_BH + bDst0, bh0 + K0);
            cp_async16(buf + OFF_BL + bDst0, bl0 + K0);
            cp_async16(buf + OFF_BH + bDst1, bh1 + K0);
            cp_async16(buf + OFF_BL + bDst1, bl1 + K0);
        }
        CP_COMMIT();  // commit even if empty: keeps group count in lockstep
    };

    issue(0);
    issue(1);

    for (int c = 0; c < 8; c++) {
        CP_WAIT1();          // stage c complete (<=1 younger group outstanding)
        __syncthreads();     // pieces visible; also: all warps done reading buf (c+2)%3

        issue(c + 2);        // prefetch with a full chunk of compute as cover

        uint32_t cur = (uint32_t)(c % NSTAGE) * BUF_SZ;
        #pragma unroll
        for (int k16 = 0; k16 < 2; k16++) {
            uint32_t ka = cur + aRow + k16 * 32;
            uint32_t kb = cur + bRow4 + k16 * 32;
            uint32_t ah[2][4], al[2][4];
            ldsm4(ah[0], sb + OFF_AH + ka);
            ldsm4(ah[1], sb + OFF_AH + ka + 16 * ASTR);
            ldsm4(al[0], sb + OFF_AL + ka);
            ldsm4(al[1], sb + OFF_AL + ka + 16 * ASTR);
            #pragma unroll
            for (int ntp = 0; ntp < 4; ntp++) {
                uint32_t bh4[4], bl4[4];
                ldsm4(bh4, sb + OFF_BH + kb + ntp * 16 * ASTR);
                ldsm4(bl4, sb + OFF_BL + kb + ntp * 16 * ASTR);
                #pragma unroll
                for (int sub = 0; sub < 2; sub++) {
                    int nt = ntp * 2 + sub;
                    #pragma unroll
                    for (int mt = 0; mt < 2; mt++) {
                        mma16816(acc[mt][nt], ah[mt], &bh4[2 * sub]);
                        mma16816(acc[mt][nt], ah[mt], &bl4[2 * sub]);
                        mma16816(acc[mt][nt], al[mt], &bh4[2 * sub]);
                    }
                }
            }
        }
    }

    // ---- epilogue: fragments -> d_G ----
    int rbase = blockIdx.x * 128 + warpM * 32 + (lane >> 2);
    int cbase = warpN * 64 + (lane & 3) * 2;
    #pragma unroll
    for (int mt = 0; mt < 2; mt++) {
        #pragma unroll
        for (int nt = 0; nt < 8; nt++) {
            float* g0 = d_G + (size_t)(rbase + mt * 16) * HH + cbase + nt * 8;
            float* g1 = g0 + 8 * HH;
            *(float2*)g0 = make_float2(acc[mt][nt][0], acc[mt][nt][1]);
            *(float2*)g1 = make_float2(acc[mt][nt][2], acc[mt][nt][3]);
        }
    }
}

// ---------------- edge pass: 16 lanes/edge, atomic segment sums -----------
__global__ void edge_kernel(const float* __restrict__ emb, const float* __restrict__ scores,
                            const int* __restrict__ src, const int* __restrict__ dst,
                            const int* __restrict__ et) {
    int eg = blockIdx.x * 16 + (threadIdx.x >> 4);
    int l = threadIdx.x & 15;
    int s = __ldg(src + eg);
    int d = __ldg(dst + eg);
    int t = __ldg(et + eg);

    const float4* gq = (const float4*)(d_G + (size_t)d * HH);
    const float4* hs = (const float4*)(emb + (size_t)s * HH);
    float acc = 0.f;
    #pragma unroll
    for (int j = 0; j < 4; j++) {
        float4 a = gq[j * 16 + l];
        float4 b = hs[j * 16 + l];
        acc += a.x * b.x + a.y * b.y + a.z * b.z + a.w * b.w;
    }
    #pragma unroll
    for (int o = 8; o > 0; o >>= 1) acc += __shfl_xor_sync(0xffffffffu, acc, o);

    if (l == 0) {
        float4 ad = d_aux[d];
        float pv = (t == 0) ? ad.x : ((t == 1) ? ad.y : ad.z);
        float u  = d_aux[s].w;
        float alpha = (acc + pv + u) * 0.0625f;  // / sqrt(256)
        float ex = expf(alpha);
        atomicAdd(&d_S[d].x, ex);
        atomicAdd(&d_S[d].y, __ldg(scores + s) * ex);
    }
}

// ---------------- per-graph logits + log-softmax + CE ---------------------
__global__ void logits_kernel(const int* __restrict__ cand, const int* __restrict__ label,
                              float* __restrict__ outLogits) {
    __shared__ float sl[CC];
    __shared__ float red[128];
    int b = blockIdx.x, tid = threadIdx.x;

    float logit = 0.f;
    if (tid < CC) {
        int node = cand[b * CC + tid];
        float2 s = d_S[node];
        logit = (s.x > 0.f) ? (s.y / s.x) : 0.f;
        sl[tid] = logit;
        outLogits[b * CC + tid] = logit;
    }
    red[tid] = (tid < CC) ? logit : -3.4e38f;
    __syncthreads();
    for (int st = 64; st > 0; st >>= 1) {
        if (tid < st) red[tid] = fmaxf(red[tid], red[tid + st]);
        __syncthreads();
    }
    float mx = red[0];
    __syncthreads();
    red[tid] = (tid < CC) ? expf(logit - mx) : 0.f;
    __syncthreads();
    for (int st = 64; st > 0; st >>= 1) {
        if (tid < st) red[tid] += red[tid + st];
        __syncthreads();
    }
    if (tid == 0) {
        int lab = label[b];
        d_lossPart[b] = -(sl[lab] - mx - logf(red[0]));
    }
}

__global__ void loss_kernel(float* __restrict__ outLoss) {
    float v = d_lossPart[threadIdx.x];  // 32 threads == BB
    #pragma unroll
    for (int o = 16; o > 0; o >>= 1) v += __shfl_xor_sync(0xffffffffu, v, o);
    if (threadIdx.x == 0) outLoss[0] = v;
}

// ---------------- launch --------------------------------------------------
extern "C" void kernel_launch(void* const* d_in, const int* in_sizes, int n_in,
                              void* d_out, int out_size) {
    const float* emb    = (const float*)d_in[0];
    const float* scores = (const float*)d_in[1];
    const float* Wl     = (const float*)d_in[2];
    const float* bl     = (const float*)d_in[3];
    const float* Wr     = (const float*)d_in[4];
    const float* br     = (const float*)d_in[5];
    const float* We     = (const float*)d_in[6];
    const float* be     = (const float*)d_in[7];
    const float* eemb   = (const float*)d_in[8];
    const int*   src    = (const int*)d_in[9];
    const int*   dst    = (const int*)d_in[10];
    const int*   et     = (const int*)d_in[11];
    const int*   cand   = (const int*)d_in[12];
    const int*   label  = (const int*)d_in[13];

    float* out = (float*)d_out;
    float* lossPtr;
    float* logitsPtr;
    if (out_size >= BB * CC + 1) {            // [loss, logits...] (tuple order)
        lossPtr = out;
        logitsPtr = out + 1;
    } else if (out_size == BB * CC) {         // logits only
        lossPtr = nullptr;
        logitsPtr = out;
    } else {                                  // loss only
        lossPtr = out;
        void* p = nullptr;
        cudaGetSymbolAddress(&p, d_logitsScratch);
        logitsPtr = (float*)p;
    }

    cudaFuncSetAttribute(gemm_mma_kernel,
                         cudaFuncAttributeMaxDynamicSharedMemorySize, S_TOTAL);

    prep_kernel<<<1, HH>>>(Wl, bl, Wr, br, We, be, eemb);
    matA_kernel<<<HH, HH>>>(Wl, Wr);
    aux_kernel<<<NN / 8, 256>>>(emb);
    gemm_mma_kernel<<<NN / 128, 512, S_TOTAL>>>();
    edge_kernel<<<EE / 16, 256>>>(emb, scores, src, dst, et);
    logits_kernel<<<BB, 128>>>(cand, label, logitsPtr);
    if (lossPtr) loss_kernel<<<1, 32>>>(lossPtr);
}

// round 16
// speedup vs baseline: 1.5905x; 1.0081x over previous
#include <cuda_runtime.h>
#include <cuda_bf16.h>
#include <math.h>
#include <stdint.h>

// Problem constants
#define BB     32
#define N_PER_ 2000
#define E_PER_ 16000
#define HH     256
#define EFD    20
#define ETN    3
#define CC     100
#define NN     (BB * N_PER_)     // 64000
#define EE     (BB * E_PER_)     // 512000

typedef unsigned long long u64;

// ---------------- cp.async helpers ----------------------------------------
__device__ __forceinline__ void cp_async16(uint32_t smem_addr, const void* gptr) {
    asm volatile("cp.async.cg.shared.global [%0], [%1], 16;"
                 :: "r"(smem_addr), "l"(gptr));
}
#define CP_COMMIT() asm volatile("cp.async.commit_group;" ::: "memory")
#define CP_WAIT1()  asm volatile("cp.async.wait_group 1;" ::: "memory")

__device__ __forceinline__ uint32_t smem_u32(const void* p) {
    uint32_t a;
    asm("{ .reg .u64 t; cvta.to.shared.u64 t, %1; cvt.u32.u64 %0, t; }"
        : "=r"(a) : "l"(p));
    return a;
}

// ---------------- warp MMA helpers (sm_80+ baseline PTX) -------------------
__device__ __forceinline__ void mma16816(float* d, const uint32_t* a, const uint32_t* b) {
    asm volatile(
        "mma.sync.aligned.m16n8k16.row.col.f32.bf16.bf16.f32 "
        "{%0,%1,%2,%3}, {%4,%5,%6,%7}, {%8,%9}, {%0,%1,%2,%3};"
        : "+f"(d[0]), "+f"(d[1]), "+f"(d[2]), "+f"(d[3])
        : "r"(a[0]), "r"(a[1]), "r"(a[2]), "r"(a[3]), "r"(b[0]), "r"(b[1]));
}
__device__ __forceinline__ void ldsm4(uint32_t* r, uint32_t addr) {
    asm volatile("ldmatrix.sync.aligned.m8n8.x4.shared.b16 {%0,%1,%2,%3}, [%4];"
        : "=r"(r[0]), "=r"(r[1]), "=r"(r[2]), "=r"(r[3]) : "r"(addr));
}

// ---------------- bf16 split helpers ---------------------------------------
__device__ __forceinline__ uint32_t bfhi2(float x0, float x1, float& r0, float& r1) {
    __nv_bfloat16 b0 = __float2bfloat16(x0), b1 = __float2bfloat16(x1);
    r0 = x0 - __bfloat162float(b0);
    r1 = x1 - __bfloat162float(b1);
    return ((uint32_t)__bfloat16_as_ushort(b1) << 16) | (uint32_t)__bfloat16_as_ushort(b0);
}
__device__ __forceinline__ uint32_t bflo2(float x0, float x1) {
    __nv_bfloat16 b0 = __float2bfloat16(x0), b1 = __float2bfloat16(x1);
    return ((uint32_t)__bfloat16_as_ushort(b1) << 16) | (uint32_t)__bfloat16_as_ushort(b0);
}

// ---------------- scratch (static device globals; no runtime alloc) -------
__device__ float          d_G[(size_t)NN * HH];       // h @ A   (65.5 MB)
__device__ __nv_bfloat16  d_Hh[(size_t)NN * HH];      // split(h) hi (32 MB)
__device__ __nv_bfloat16  d_Hl[(size_t)NN * HH];      // split(h) lo (32 MB)
__device__ __nv_bfloat16  d_Bh[HH * HH];              // split(A^T) hi [n][k]
__device__ __nv_bfloat16  d_Bl[HH * HH];              // split(A^T) lo [n][k]
__device__ float  d_wk2[ETN][HH];          // Wl^T K2_t
__device__ float  d_wu[HH];                // Wr^T bl
__device__ float  d_wv[HH];                // Wl^T br
__device__ float  d_consts[ETN];           // bl.K2_t + bl.br
__device__ float4 d_aux[NN];               // (p0+v+c0, p1+v+c1, p2+v+c2, u)
__device__ float2 d_S[NN];                 // (sum exp, sum scores*exp)
__device__ float  d_lossPart[BB];
__device__ float  d_logitsScratch[BB * CC];

// ---------------- prep: gelu(edge_emb), K2 table, folded bias vectors -----
__global__ void prep_kernel(const float* __restrict__ Wl, const float* __restrict__ bl,
                            const float* __restrict__ Wr, const float* __restrict__ br,
                            const float* __restrict__ We, const float* __restrict__ be,
                            const float* __restrict__ eemb) {
    __shared__ float s_ef[ETN][EFD];
    __shared__ float s_K2[ETN][HH];
    __shared__ float s_bl[HH], s_br[HH];
    int tid = threadIdx.x;  // 256 threads

    if (tid < ETN * EFD) {
        float x = eemb[tid];
        s_ef[tid / EFD][tid % EFD] = 0.5f * x * (1.0f + erff(x * 0.70710678118654752f));
    }
    s_bl[tid] = bl[tid];
    s_br[tid] = br[tid];
    __syncthreads();

    float bei = be[tid];
    #pragma unroll
    for (int t = 0; t < ETN; t++) {
        float a = bei;
        #pragma unroll
        for (int j = 0; j < EFD; j++) a += We[tid * EFD + j] * s_ef[t][j];
        s_K2[t][tid] = a;
    }
    __syncthreads();

    float p0 = 0.f, p1 = 0.f, p2 = 0.f, v = 0.f, u = 0.f;
    for (int k = 0; k < HH; k++) {
        float wl = Wl[k * HH + tid];
        float wr = Wr[k * HH + tid];
        p0 += wl * s_K2[0][k];
        p1 += wl * s_K2[1][k];
        p2 += wl * s_K2[2][k];
        v  += wl * s_br[k];
        u  += wr * s_bl[k];
    }
    d_wk2[0][tid] = p0;
    d_wk2[1][tid] = p1;
    d_wk2[2][tid] = p2;
    d_wv[tid] = v;
    d_wu[tid] = u;

    if (tid < ETN) {
        float r = 0.f, bb2 = 0.f;
        for (int k = 0; k < HH; k++) {
            r   += s_bl[k] * s_K2[tid][k];
            bb2 += s_bl[k] * s_br[k];
        }
        d_consts[tid] = r + bb2;
    }
}

// ---------------- A = Wl^T @ Wr, emitted as bf16-split B^T ops ------------
__global__ void matA_kernel(const float* __restrict__ Wl, const float* __restrict__ Wr) {
    __shared__ float col[HH];
    int i = blockIdx.x;   // k index (A row)
    int j = threadIdx.x;  // n index (A col)
    col[j] = Wl[j * HH + i];
    __syncthreads();
    float acc = 0.f;
    #pragma unroll 8
    for (int k = 0; k < HH; k++) acc = fmaf(col[k], Wr[k * HH + j], acc);
    __nv_bfloat16 h = __float2bfloat16(acc);
    d_Bh[j * HH + i] = h;
    d_Bl[j * HH + i] = __float2bfloat16(acc - __bfloat162float(h));
}

// ---------------- aux per-node table + H bf16 split + zero S --------------
__global__ void aux_kernel(const float* __restrict__ emb) {
    __shared__ float4 w[5][64];
    __shared__ float  sc[ETN];
    int tid = threadIdx.x;
    if (tid < 64) {
        w[0][tid] = ((const float4*)d_wk2[0])[tid];
        w[1][tid] = ((const float4*)d_wk2[1])[tid];
        w[2][tid] = ((const float4*)d_wk2[2])[tid];
        w[3][tid] = ((const float4*)d_wv)[tid];
        w[4][tid] = ((const float4*)d_wu)[tid];
    }
    if (tid < ETN) sc[tid] = d_consts[tid];
    __syncthreads();

    int warp = tid >> 5, lane = tid & 31;
    int n = blockIdx.x * 8 + warp;
    const float4* hp = (const float4*)(emb + (size_t)n * HH);
    float4 h0 = hp[lane];
    float4 h1 = hp[32 + lane];

    // ---- emit bf16 hi/lo split of h ----
    {
        float r0, r1, r2, r3;
        uint2 hi0, hi1, lo0, lo1;
        hi0.x = bfhi2(h0.x, h0.y, r0, r1);
        hi0.y = bfhi2(h0.z, h0.w, r2, r3);
        lo0.x = bflo2(r0, r1);
        lo0.y = bflo2(r2, r3);
        hi1.x = bfhi2(h1.x, h1.y, r0, r1);
        hi1.y = bfhi2(h1.z, h1.w, r2, r3);
        lo1.x = bflo2(r0, r1);
        lo1.y = bflo2(r2, r3);
        uint2* hh = (uint2*)(d_Hh + (size_t)n * HH);
        uint2* hl = (uint2*)(d_Hl + (size_t)n * HH);
        hh[lane] = hi0;
        hh[32 + lane] = hi1;
        hl[lane] = lo0;
        hl[32 + lane] = lo1;
    }

    float acc[5];
    #pragma unroll
    for (int q = 0; q < 5; q++) {
        float4 a = w[q][lane];
        float4 b = w[q][32 + lane];
        acc[q] = h0.x * a.x + h0.y * a.y + h0.z * a.z + h0.w * a.w
               + h1.x * b.x + h1.y * b.y + h1.z * b.z + h1.w * b.w;
    }
    #pragma unroll
    for (int o = 16; o > 0; o >>= 1) {
        #pragma unroll
        for (int q = 0; q < 5; q++) acc[q] += __shfl_xor_sync(0xffffffffu, acc[q], o);
    }
    if (lane == 0) {
        d_aux[n] = make_float4(acc[0] + acc[3] + sc[0],
                               acc[1] + acc[3] + sc[1],
                               acc[2] + acc[3] + sc[2],
                               acc[4]);
        d_S[n] = make_float2(0.f, 0.f);
    }
}

// ---------------- G = h @ A via bf16 3-split mma.sync ----------------------
// 2 CTAs/SM: tile M=128 x N=128, 256 threads (8 warps, warp 32x64),
// 2-stage cp.async pipeline (80KB smem/CTA). Cross-CTA overlap hides the
// per-chunk barriers that convoyed the single-CTA version.
#define KC      32
#define ASTR    80
#define A_BYTES (128 * ASTR)      // 10240 per split
#define B_BYTES (128 * ASTR)      // 10240 per split
#define OFF_AH  0
#define OFF_AL  A_BYTES
#define OFF_BH  (2 * A_BYTES)
#define OFF_BL  (2 * A_BYTES + B_BYTES)
#define BUF_SZ  (2 * A_BYTES + 2 * B_BYTES)   // 40960
#define NSTAGE  2
#define S_TOTAL (NSTAGE * BUF_SZ)             // 81920

__global__ __launch_bounds__(256, 2)
void gemm_mma_kernel() {
    extern __shared__ char smem[];
    uint32_t sb = smem_u32(smem);
    int tid = threadIdx.x, wid = tid >> 5, lane = tid & 31;
    int warpM = wid & 3, warpN = wid >> 2;   // warpN in 0..1

    // fill-role indices: 256 threads cover 64 rows per pass -> 2 passes each
    int pr = tid >> 2, pq = tid & 3;
    size_t mBase = (size_t)blockIdx.x * 128;
    int nBase = blockIdx.y * 128;

    const __nv_bfloat16* ah0 = d_Hh + (mBase + pr) * HH + pq * 8;
    const __nv_bfloat16* al0 = d_Hl + (mBase + pr) * HH + pq * 8;
    const __nv_bfloat16* bh0 = d_Bh + (size_t)(nBase + pr) * HH + pq * 8;
    const __nv_bfloat16* bl0 = d_Bl + (size_t)(nBase + pr) * HH + pq * 8;
    const size_t row64 = (size_t)64 * HH;
    uint32_t d0 = (uint32_t)pr * ASTR + (uint32_t)pq * 16;
    uint32_t d1 = d0 + 64 * ASTR;

    float acc[2][8][4];
    #pragma unroll
    for (int m = 0; m < 2; m++)
        #pragma unroll
        for (int n = 0; n < 8; n++)
            #pragma unroll
            for (int j = 0; j < 4; j++) acc[m][n][j] = 0.f;

    // ldmatrix base offsets (within a buffer)
    uint32_t aRow = (uint32_t)(warpM * 32 + (lane & 15)) * ASTR + ((lane >> 4) * 8) * 2;
    // B x4: matrices {nt_even.k0, nt_even.k1, nt_odd.k0, nt_odd.k1}
    uint32_t bRow4 = (uint32_t)(warpN * 64 + ((lane >> 4) & 1) * 8 + (lane & 7)) * ASTR
                   + (((lane >> 3) & 1) * 8) * 2;

    auto issue = [&](int c) {
        if (c < 8) {
            uint32_t buf = sb + (uint32_t)(c % NSTAGE) * BUF_SZ;
            int K0 = c * KC;
            cp_async16(buf + OFF_AH + d0, ah0 + K0);
            cp_async16(buf + OFF_AH + d1, ah0 + row64 + K0);
            cp_async16(buf + OFF_AL + d0, al0 + K0);
            cp_async16(buf + OFF_AL + d1, al0 + row64 + K0);
            cp_async16(buf + OFF_BH + d0, bh0 + K0);
            cp_async16(buf + OFF_BH + d1, bh0 + row64 + K0);
            cp_async16(buf + OFF_BL + d0, bl0 + K0);
            cp_async16(buf + OFF_BL + d1, bl0 + row64 + K0);
        }
        CP_COMMIT();  // commit even if empty: keeps group count in lockstep
    };

    issue(0);
    issue(1);

    for (int c = 0; c < 8; c++) {
        CP_WAIT1();          // stage c complete (<=1 younger group outstanding)
        __syncthreads();

        uint32_t cur = sb + (uint32_t)(c % NSTAGE) * BUF_SZ;
        #pragma unroll
        for (int k16 = 0; k16 < 2; k16++) {
            uint32_t ka = cur + aRow + k16 * 32;
            uint32_t kb = cur + bRow4 + k16 * 32;
            uint32_t ah[2][4], al[2][4];
            ldsm4(ah[0], ka + OFF_AH);
            ldsm4(ah[1], ka + OFF_AH + 16 * ASTR);
            ldsm4(al[0], ka + OFF_AL);
            ldsm4(al[1], ka + OFF_AL + 16 * ASTR);
            #pragma unroll
            for (int ntp = 0; ntp < 4; ntp++) {
                uint32_t bh4[4], bl4[4];
                ldsm4(bh4, kb + OFF_BH + ntp * 16 * ASTR);
                ldsm4(bl4, kb + OFF_BL + ntp * 16 * ASTR);
                #pragma unroll
                for (int sub = 0; sub < 2; sub++) {
                    int nt = ntp * 2 + sub;
                    #pragma unroll
                    for (int mt = 0; mt < 2; mt++) {
                        mma16816(acc[mt][nt], ah[mt], &bh4[2 * sub]);
                        mma16816(acc[mt][nt], ah[mt], &bl4[2 * sub]);
                        mma16816(acc[mt][nt], al[mt], &bh4[2 * sub]);
                    }
                }
            }
        }
        __syncthreads();     // buffer c%2 fully consumed
        issue(c + 2);        // refill it
    }

    // ---- epilogue: fragments -> d_G ----
    int rbase = (int)mBase + warpM * 32 + (lane >> 2);
    int cbase = nBase + warpN * 64 + (lane & 3) * 2;
    #pragma unroll
    for (int mt = 0; mt < 2; mt++) {
        #pragma unroll
        for (int nt = 0; nt < 8; nt++) {
            float* g0 = d_G + (size_t)(rbase + mt * 16) * HH + cbase + nt * 8;
            float* g1 = g0 + 8 * HH;
            *(float2*)g0 = make_float2(acc[mt][nt][0], acc[mt][nt][1]);
            *(float2*)g1 = make_float2(acc[mt][nt][2], acc[mt][nt][3]);
        }
    }
}

// ---------------- edge pass: 16 lanes/edge, atomic segment sums -----------
__global__ void edge_kernel(const float* __restrict__ emb, const float* __restrict__ scores,
                            const int* __restrict__ src, const int* __restrict__ dst,
                            const int* __restrict__ et) {
    int eg = blockIdx.x * 16 + (threadIdx.x >> 4);
    int l = threadIdx.x & 15;
    int s = __ldg(src + eg);
    int d = __ldg(dst + eg);
    int t = __ldg(et + eg);

    const float4* gq = (const float4*)(d_G + (size_t)d * HH);
    const float4* hs = (const float4*)(emb + (size_t)s * HH);
    float acc = 0.f;
    #pragma unroll
    for (int j = 0; j < 4; j++) {
        float4 a = gq[j * 16 + l];
        float4 b = hs[j * 16 + l];
        acc += a.x * b.x + a.y * b.y + a.z * b.z + a.w * b.w;
    }
    #pragma unroll
    for (int o = 8; o > 0; o >>= 1) acc += __shfl_xor_sync(0xffffffffu, acc, o);

    if (l == 0) {
        float4 ad = d_aux[d];
        float pv = (t == 0) ? ad.x : ((t == 1) ? ad.y : ad.z);
        float u  = d_aux[s].w;
        float alpha = (acc + pv + u) * 0.0625f;  // / sqrt(256)
        float ex = expf(alpha);
        atomicAdd(&d_S[d].x, ex);
        atomicAdd(&d_S[d].y, __ldg(scores + s) * ex);
    }
}

// ---------------- per-graph logits + log-softmax + CE ---------------------
__global__ void logits_kernel(const int* __restrict__ cand, const int* __restrict__ label,
                              float* __restrict__ outLogits) {
    __shared__ float sl[CC];
    __shared__ float red[128];
    int b = blockIdx.x, tid = threadIdx.x;

    float logit = 0.f;
    if (tid < CC) {
        int node = cand[b * CC + tid];
        float2 s = d_S[node];
        logit = (s.x > 0.f) ? (s.y / s.x) : 0.f;
        sl[tid] = logit;
        outLogits[b * CC + tid] = logit;
    }
    red[tid] = (tid < CC) ? logit : -3.4e38f;
    __syncthreads();
    for (int st = 64; st > 0; st >>= 1) {
        if (tid < st) red[tid] = fmaxf(red[tid], red[tid + st]);
        __syncthreads();
    }
    float mx = red[0];
    __syncthreads();
    red[tid] = (tid < CC) ? expf(logit - mx) : 0.f;
    __syncthreads();
    for (int st = 64; st > 0; st >>= 1) {
        if (tid < st) red[tid] += red[tid + st];
        __syncthreads();
    }
    if (tid == 0) {
        int lab = label[b];
        d_lossPart[b] = -(sl[lab] - mx - logf(red[0]));
    }
}

__global__ void loss_kernel(float* __restrict__ outLoss) {
    float v = d_lossPart[threadIdx.x];  // 32 threads == BB
    #pragma unroll
    for (int o = 16; o > 0; o >>= 1) v += __shfl_xor_sync(0xffffffffu, v, o);
    if (threadIdx.x == 0) outLoss[0] = v;
}

// ---------------- launch --------------------------------------------------
extern "C" void kernel_launch(void* const* d_in, const int* in_sizes, int n_in,
                              void* d_out, int out_size) {
    const float* emb    = (const float*)d_in[0];
    const float* scores = (const float*)d_in[1];
    const float* Wl     = (const float*)d_in[2];
    const float* bl     = (const float*)d_in[3];
    const float* Wr     = (const float*)d_in[4];
    const float* br     = (const float*)d_in[5];
    const float* We     = (const float*)d_in[6];
    const float* be     = (const float*)d_in[7];
    const float* eemb   = (const float*)d_in[8];
    const int*   src    = (const int*)d_in[9];
    const int*   dst    = (const int*)d_in[10];
    const int*   et     = (const int*)d_in[11];
    const int*   cand   = (const int*)d_in[12];
    const int*   label  = (const int*)d_in[13];

    float* out = (float*)d_out;
    float* lossPtr;
    float* logitsPtr;
    if (out_size >= BB * CC + 1) {            // [loss, logits...] (tuple order)
        lossPtr = out;
        logitsPtr = out + 1;
    } else if (out_size == BB * CC) {         // logits only
        lossPtr = nullptr;
        logitsPtr = out;
    } else {                                  // loss only
        lossPtr = out;
        void* p = nullptr;
        cudaGetSymbolAddress(&p, d_logitsScratch);
        logitsPtr = (float*)p;
    }

    cudaFuncSetAttribute(gemm_mma_kernel,
                         cudaFuncAttributeMaxDynamicSharedMemorySize, S_TOTAL);

    prep_kernel<<<1, HH>>>(Wl, bl, Wr, br, We, be, eemb);
    matA_kernel<<<HH, HH>>>(Wl, Wr);
    aux_kernel<<<NN / 8, 256>>>(emb);
    gemm_mma_kernel<<<dim3(NN / 128, 2), 256, S_TOTAL>>>();
    edge_kernel<<<EE / 16, 256>>>(emb, scores, src, dst, et);
    logits_kernel<<<BB, 128>>>(cand, label, logitsPtr);
    if (lossPtr) loss_kernel<<<1, 32>>>(lossPtr);
}

// round 17
// speedup vs baseline: 1.7574x; 1.1049x over previous
#include <cuda_runtime.h>
#include <cuda_bf16.h>
#include <math.h>
#include <stdint.h>

// Problem constants
#define BB     32
#define N_PER_ 2000
#define E_PER_ 16000
#define HH     256
#define EFD    20
#define ETN    3
#define CC     100
#define NN     (BB * N_PER_)     // 64000
#define EE     (BB * E_PER_)     // 512000

typedef unsigned long long u64;

// ---------------- cp.async helpers ----------------------------------------
__device__ __forceinline__ void cp_async16(uint32_t smem_addr, const void* gptr) {
    asm volatile("cp.async.cg.shared.global [%0], [%1], 16;"
                 :: "r"(smem_addr), "l"(gptr));
}
#define CP_COMMIT() asm volatile("cp.async.commit_group;" ::: "memory")
#define CP_WAIT1()  asm volatile("cp.async.wait_group 1;" ::: "memory")

__device__ __forceinline__ uint32_t smem_u32(const void* p) {
    uint32_t a;
    asm("{ .reg .u64 t; cvta.to.shared.u64 t, %1; cvt.u32.u64 %0, t; }"
        : "=r"(a) : "l"(p));
    return a;
}

// ---------------- warp MMA helpers (sm_80+ baseline PTX) -------------------
__device__ __forceinline__ void mma16816(float* d, const uint32_t* a, const uint32_t* b) {
    asm volatile(
        "mma.sync.aligned.m16n8k16.row.col.f32.bf16.bf16.f32 "
        "{%0,%1,%2,%3}, {%4,%5,%6,%7}, {%8,%9}, {%0,%1,%2,%3};"
        : "+f"(d[0]), "+f"(d[1]), "+f"(d[2]), "+f"(d[3])
        : "r"(a[0]), "r"(a[1]), "r"(a[2]), "r"(a[3]), "r"(b[0]), "r"(b[1]));
}
__device__ __forceinline__ void ldsm4(uint32_t* r, uint32_t addr) {
    asm volatile("ldmatrix.sync.aligned.m8n8.x4.shared.b16 {%0,%1,%2,%3}, [%4];"
        : "=r"(r[0]), "=r"(r[1]), "=r"(r[2]), "=r"(r[3]) : "r"(addr));
}

// ---------------- bf16 split helpers ---------------------------------------
__device__ __forceinline__ uint32_t bfhi2(float x0, float x1, float& r0, float& r1) {
    __nv_bfloat16 b0 = __float2bfloat16(x0), b1 = __float2bfloat16(x1);
    r0 = x0 - __bfloat162float(b0);
    r1 = x1 - __bfloat162float(b1);
    return ((uint32_t)__bfloat16_as_ushort(b1) << 16) | (uint32_t)__bfloat16_as_ushort(b0);
}
__device__ __forceinline__ uint32_t bflo2(float x0, float x1) {
    __nv_bfloat16 b0 = __float2bfloat16(x0), b1 = __float2bfloat16(x1);
    return ((uint32_t)__bfloat16_as_ushort(b1) << 16) | (uint32_t)__bfloat16_as_ushort(b0);
}

// ---------------- scratch (static device globals; no runtime alloc) -------
__device__ float          d_G[(size_t)NN * HH];       // h @ A   (65.5 MB)
__device__ __nv_bfloat16  d_Hh[(size_t)NN * HH];      // split(h) hi (32 MB)
__device__ __nv_bfloat16  d_Hl[(size_t)NN * HH];      // split(h) lo (32 MB)
__device__ __nv_bfloat16  d_Bh[HH * HH];              // split(A^T) hi [n][k]
__device__ __nv_bfloat16  d_Bl[HH * HH];              // split(A^T) lo [n][k]
__device__ float  d_K2[ETN * HH];          // K2 table (prep1 -> prep2)
__device__ float  d_wk2[ETN][HH];          // Wl^T K2_t
__device__ float  d_wu[HH];                // Wr^T bl
__device__ float  d_wv[HH];                // Wl^T br
__device__ float  d_consts[ETN];           // bl.K2_t + bl.br
__device__ float4 d_aux[NN];               // (p0+v+c0, p1+v+c1, p2+v+c2, u)
__device__ float2 d_S[NN];                 // (sum exp, sum scores*exp)
__device__ float  d_lossPart[BB];
__device__ float  d_logitsScratch[BB * CC];
// CSR scratch
__device__ int      d_cnt[NN];
__device__ int      d_ptr[NN];
__device__ int      d_fill[NN];
__device__ int      d_bsum[256];
__device__ int      d_boff[256];
__device__ uint32_t d_ei[EE];              // packed src | (etype<<17)

// ---------------- prep1: gelu(edge_emb) -> K2 table + consts --------------
__global__ void prep1_kernel(const float* __restrict__ We, const float* __restrict__ be,
                             const float* __restrict__ eemb, const float* __restrict__ bl,
                             const float* __restrict__ br) {
    __shared__ float s_ef[ETN][EFD];
    __shared__ float red[256];
    int tid = threadIdx.x;  // 256 threads

    if (tid < ETN * EFD) {
        float x = eemb[tid];
        s_ef[tid / EFD][tid % EFD] = 0.5f * x * (1.0f + erff(x * 0.70710678118654752f));
    }
    __syncthreads();

    float bei = be[tid];
    float kv[ETN];
    #pragma unroll
    for (int t = 0; t < ETN; t++) {
        float a = bei;
        #pragma unroll
        for (int j = 0; j < EFD; j++) a += We[tid * EFD + j] * s_ef[t][j];
        d_K2[t * HH + tid] = a;
        kv[t] = a;
    }

    float blv = bl[tid], brv = br[tid];
    float cs[4];
    #pragma unroll
    for (int q = 0; q < 4; q++) {
        float v = (q < 3) ? blv * kv[q] : blv * brv;
        red[tid] = v;
        __syncthreads();
        for (int st = 128; st > 0; st >>= 1) {
            if (tid < st) red[tid] += red[tid + st];
            __syncthreads();
        }
        cs[q] = red[0];
        __syncthreads();
    }
    if (tid < ETN) d_consts[tid] = cs[tid] + cs[3];
}

// ---------------- prep2: folded bias vectors (256 blocks wide) ------------
__global__ void prep2_kernel(const float* __restrict__ Wl, const float* __restrict__ Wr,
                             const float* __restrict__ bl, const float* __restrict__ br) {
    __shared__ float sm[5][256];
    int j = blockIdx.x, k = threadIdx.x;
    float wl = Wl[k * HH + j];
    float wr = Wr[k * HH + j];
    sm[0][k] = wl * d_K2[0 * HH + k];
    sm[1][k] = wl * d_K2[1 * HH + k];
    sm[2][k] = wl * d_K2[2 * HH + k];
    sm[3][k] = wl * br[k];
    sm[4][k] = wr * bl[k];
    __syncthreads();
    for (int st = 128; st > 0; st >>= 1) {
        if (k < st) {
            #pragma unroll
            for (int q = 0; q < 5; q++) sm[q][k] += sm[q][k + st];
        }
        __syncthreads();
    }
    if (k == 0) {
        d_wk2[0][j] = sm[0][0];
        d_wk2[1][j] = sm[1][0];
        d_wk2[2][j] = sm[2][0];
        d_wv[j] = sm[3][0];
        d_wu[j] = sm[4][0];
    }
}

// ---------------- A = Wl^T @ Wr, emitted as bf16-split B^T ops ------------
__global__ void matA_kernel(const float* __restrict__ Wl, const float* __restrict__ Wr) {
    __shared__ float col[HH];
    int i = blockIdx.x;   // k index (A row)
    int j = threadIdx.x;  // n index (A col)
    col[j] = Wl[j * HH + i];
    __syncthreads();
    float acc = 0.f;
    #pragma unroll 8
    for (int k = 0; k < HH; k++) acc = fmaf(col[k], Wr[k * HH + j], acc);
    __nv_bfloat16 h = __float2bfloat16(acc);
    d_Bh[j * HH + i] = h;
    d_Bl[j * HH + i] = __float2bfloat16(acc - __bfloat162float(h));
}

// ---------------- aux per-node table + H bf16 split + zero cnt ------------
__global__ void aux_kernel(const float* __restrict__ emb) {
    __shared__ float4 w[5][64];
    __shared__ float  sc[ETN];
    int tid = threadIdx.x;
    if (tid < 64) {
        w[0][tid] = ((const float4*)d_wk2[0])[tid];
        w[1][tid] = ((const float4*)d_wk2[1])[tid];
        w[2][tid] = ((const float4*)d_wk2[2])[tid];
        w[3][tid] = ((const float4*)d_wv)[tid];
        w[4][tid] = ((const float4*)d_wu)[tid];
    }
    if (tid < ETN) sc[tid] = d_consts[tid];
    __syncthreads();

    int warp = tid >> 5, lane = tid & 31;
    int n = blockIdx.x * 8 + warp;
    const float4* hp = (const float4*)(emb + (size_t)n * HH);
    float4 h0 = hp[lane];
    float4 h1 = hp[32 + lane];

    // ---- emit bf16 hi/lo split of h ----
    {
        float r0, r1, r2, r3;
        uint2 hi0, hi1, lo0, lo1;
        hi0.x = bfhi2(h0.x, h0.y, r0, r1);
        hi0.y = bfhi2(h0.z, h0.w, r2, r3);
        lo0.x = bflo2(r0, r1);
        lo0.y = bflo2(r2, r3);
        hi1.x = bfhi2(h1.x, h1.y, r0, r1);
        hi1.y = bfhi2(h1.z, h1.w, r2, r3);
        lo1.x = bflo2(r0, r1);
        lo1.y = bflo2(r2, r3);
        uint2* hh = (uint2*)(d_Hh + (size_t)n * HH);
        uint2* hl = (uint2*)(d_Hl + (size_t)n * HH);
        hh[lane] = hi0;
        hh[32 + lane] = hi1;
        hl[lane] = lo0;
        hl[32 + lane] = lo1;
    }

    float acc[5];
    #pragma unroll
    for (int q = 0; q < 5; q++) {
        float4 a = w[q][lane];
        float4 b = w[q][32 + lane];
        acc[q] = h0.x * a.x + h0.y * a.y + h0.z * a.z + h0.w * a.w
               + h1.x * b.x + h1.y * b.y + h1.z * b.z + h1.w * b.w;
    }
    #pragma unroll
    for (int o = 16; o > 0; o >>= 1) {
        #pragma unroll
        for (int q = 0; q < 5; q++) acc[q] += __shfl_xor_sync(0xffffffffu, acc[q], o);
    }
    if (lane == 0) {
        d_aux[n] = make_float4(acc[0] + acc[3] + sc[0],
                               acc[1] + acc[3] + sc[1],
                               acc[2] + acc[3] + sc[2],
                               acc[4]);
        d_cnt[n] = 0;
    }
}

// ---------------- G = h @ A via bf16 3-split mma.sync ----------------------
// 2 CTAs/SM: tile M=128 x N=128, 256 threads (8 warps, warp 32x64).
#define KC      32
#define ASTR    80
#define A_BYTES (128 * ASTR)      // 10240 per split
#define B_BYTES (128 * ASTR)      // 10240 per split
#define OFF_AH  0
#define OFF_AL  A_BYTES
#define OFF_BH  (2 * A_BYTES)
#define OFF_BL  (2 * A_BYTES + B_BYTES)
#define BUF_SZ  (2 * A_BYTES + 2 * B_BYTES)   // 40960
#define NSTAGE  2
#define S_TOTAL (NSTAGE * BUF_SZ)             // 81920

__global__ __launch_bounds__(256, 2)
void gemm_mma_kernel() {
    extern __shared__ char smem[];
    uint32_t sb = smem_u32(smem);
    int tid = threadIdx.x, wid = tid >> 5, lane = tid & 31;
    int warpM = wid & 3, warpN = wid >> 2;   // warpN in 0..1

    int pr = tid >> 2, pq = tid & 3;
    size_t mBase = (size_t)blockIdx.x * 128;
    int nBase = blockIdx.y * 128;

    const __nv_bfloat16* ah0 = d_Hh + (mBase + pr) * HH + pq * 8;
    const __nv_bfloat16* al0 = d_Hl + (mBase + pr) * HH + pq * 8;
    const __nv_bfloat16* bh0 = d_Bh + (size_t)(nBase + pr) * HH + pq * 8;
    const __nv_bfloat16* bl0 = d_Bl + (size_t)(nBase + pr) * HH + pq * 8;
    const size_t row64 = (size_t)64 * HH;
    uint32_t d0 = (uint32_t)pr * ASTR + (uint32_t)pq * 16;
    uint32_t d1 = d0 + 64 * ASTR;

    float acc[2][8][4];
    #pragma unroll
    for (int m = 0; m < 2; m++)
        #pragma unroll
        for (int n = 0; n < 8; n++)
            #pragma unroll
            for (int j = 0; j < 4; j++) acc[m][n][j] = 0.f;

    uint32_t aRow = (uint32_t)(warpM * 32 + (lane & 15)) * ASTR + ((lane >> 4) * 8) * 2;
    uint32_t bRow4 = (uint32_t)(warpN * 64 + ((lane >> 4) & 1) * 8 + (lane & 7)) * ASTR
                   + (((lane >> 3) & 1) * 8) * 2;

    auto issue = [&](int c) {
        if (c < 8) {
            uint32_t buf = sb + (uint32_t)(c % NSTAGE) * BUF_SZ;
            int K0 = c * KC;
            cp_async16(buf + OFF_AH + d0, ah0 + K0);
            cp_async16(buf + OFF_AH + d1, ah0 + row64 + K0);
            cp_async16(buf + OFF_AL + d0, al0 + K0);
            cp_async16(buf + OFF_AL + d1, al0 + row64 + K0);
            cp_async16(buf + OFF_BH + d0, bh0 + K0);
            cp_async16(buf + OFF_BH + d1, bh0 + row64 + K0);
            cp_async16(buf + OFF_BL + d0, bl0 + K0);
            cp_async16(buf + OFF_BL + d1, bl0 + row64 + K0);
        }
        CP_COMMIT();
    };

    issue(0);
    issue(1);

    for (int c = 0; c < 8; c++) {
        CP_WAIT1();
        __syncthreads();

        uint32_t cur = sb + (uint32_t)(c % NSTAGE) * BUF_SZ;
        #pragma unroll
        for (int k16 = 0; k16 < 2; k16++) {
            uint32_t ka = cur + aRow + k16 * 32;
            uint32_t kb = cur + bRow4 + k16 * 32;
            uint32_t ah[2][4], al[2][4];
            ldsm4(ah[0], ka + OFF_AH);
            ldsm4(ah[1], ka + OFF_AH + 16 * ASTR);
            ldsm4(al[0], ka + OFF_AL);
            ldsm4(al[1], ka + OFF_AL + 16 * ASTR);
            #pragma unroll
            for (int ntp = 0; ntp < 4; ntp++) {
                uint32_t bh4[4], bl4[4];
                ldsm4(bh4, kb + OFF_BH + ntp * 16 * ASTR);
                ldsm4(bl4, kb + OFF_BL + ntp * 16 * ASTR);
                #pragma unroll
                for (int sub = 0; sub < 2; sub++) {
                    int nt = ntp * 2 + sub;
                    #pragma unroll
                    for (int mt = 0; mt < 2; mt++) {
                        mma16816(acc[mt][nt], ah[mt], &bh4[2 * sub]);
                        mma16816(acc[mt][nt], ah[mt], &bl4[2 * sub]);
                        mma16816(acc[mt][nt], al[mt], &bh4[2 * sub]);
                    }
                }
            }
        }
        __syncthreads();
        issue(c + 2);
    }

    int rbase = (int)mBase + warpM * 32 + (lane >> 2);
    int cbase = nBase + warpN * 64 + (lane & 3) * 2;
    #pragma unroll
    for (int mt = 0; mt < 2; mt++) {
        #pragma unroll
        for (int nt = 0; nt < 8; nt++) {
            float* g0 = d_G + (size_t)(rbase + mt * 16) * HH + cbase + nt * 8;
            float* g1 = g0 + 8 * HH;
            *(float2*)g0 = make_float2(acc[mt][nt][0], acc[mt][nt][1]);
            *(float2*)g1 = make_float2(acc[mt][nt][2], acc[mt][nt][3]);
        }
    }
}

// ---------------- CSR build: count / scan / scatter ------------------------
__global__ void count_kernel(const int* __restrict__ dst) {
    int e = blockIdx.x * 256 + threadIdx.x;
    atomicAdd(&d_cnt[dst[e]], 1);
}

__global__ void scanA_kernel() {   // 250 blocks: per-block sums
    __shared__ int s[256];
    int tid = threadIdx.x;
    s[tid] = d_cnt[blockIdx.x * 256 + tid];
    __syncthreads();
    for (int st = 128; st > 0; st >>= 1) {
        if (tid < st) s[tid] += s[tid + st];
        __syncthreads();
    }
    if (tid == 0) d_bsum[blockIdx.x] = s[0];
}

__global__ void scanB_kernel() {   // 1 block: exclusive scan of 250 block sums
    __shared__ int s[256];
    int tid = threadIdx.x;
    int orig = (tid < 250) ? d_bsum[tid] : 0;
    s[tid] = orig;
    __syncthreads();
    for (int o = 1; o < 256; o <<= 1) {
        int v = (tid >= o) ? s[tid - o] : 0;
        __syncthreads();
        s[tid] += v;
        __syncthreads();
    }
    if (tid < 250) d_boff[tid] = s[tid] - orig;
}

__global__ void scanC_kernel() {   // 250 blocks: in-block exclusive scan + offset
    __shared__ int s[256];
    int tid = threadIdx.x;
    int n = blockIdx.x * 256 + tid;
    int c = d_cnt[n];
    s[tid] = c;
    __syncthreads();
    for (int o = 1; o < 256; o <<= 1) {
        int v = (tid >= o) ? s[tid - o] : 0;
        __syncthreads();
        s[tid] += v;
        __syncthreads();
    }
    int p = d_boff[blockIdx.x] + s[tid] - c;
    d_ptr[n] = p;
    d_fill[n] = p;
}

__global__ void scatter_kernel(const int* __restrict__ src, const int* __restrict__ dst,
                               const int* __restrict__ et) {
    int e = blockIdx.x * 256 + threadIdx.x;
    int d = dst[e];
    int pos = atomicAdd(&d_fill[d], 1);
    d_ei[pos] = (uint32_t)src[e] | ((uint32_t)et[e] << 17);
}

// ---------------- edge pass: warp-per-dst over CSR, no atomics ------------
__global__ void edge_csr_kernel(const float* __restrict__ emb,
                                const float* __restrict__ scores) {
    int n = blockIdx.x * 8 + (threadIdx.x >> 5);
    int lane = threadIdx.x & 31;
    int deg = d_cnt[n];
    int base = d_ptr[n];

    const float4* gq = (const float4*)(d_G + (size_t)n * HH);
    float4 g0 = gq[lane], g1 = gq[32 + lane];

    float4 ad = make_float4(0.f, 0.f, 0.f, 0.f);
    if (lane == 0) ad = d_aux[n];
    float se = 0.f, ss = 0.f;

    for (int i = 0; i < deg; i++) {
        uint32_t packed = __ldg(d_ei + base + i);
        int s = (int)(packed & 0x1FFFFu);
        int t = (int)(packed >> 17);
        const float4* hs = (const float4*)(emb + (size_t)s * HH);
        float4 b0 = hs[lane], b1 = hs[32 + lane];
        float acc = g0.x * b0.x + g0.y * b0.y + g0.z * b0.z + g0.w * b0.w
                  + g1.x * b1.x + g1.y * b1.y + g1.z * b1.z + g1.w * b1.w;
        #pragma unroll
        for (int o = 16; o > 0; o >>= 1) acc += __shfl_xor_sync(0xffffffffu, acc, o);

        if (lane == 0) {
            float pv = (t == 0) ? ad.x : ((t == 1) ? ad.y : ad.z);
            float u = __ldg(((const float*)(d_aux + s)) + 3);
            float alpha = (acc + pv + u) * 0.0625f;  // / sqrt(256)
            float ex = expf(alpha);
            se += ex;
            ss += __ldg(scores + s) * ex;
        }
    }
    if (lane == 0) d_S[n] = make_float2(se, ss);
}

// ---------------- per-graph logits + log-softmax + CE ---------------------
__global__ void logits_kernel(const int* __restrict__ cand, const int* __restrict__ label,
                              float* __restrict__ outLogits) {
    __shared__ float sl[CC];
    __shared__ float red[128];
    int b = blockIdx.x, tid = threadIdx.x;

    float logit = 0.f;
    if (tid < CC) {
        int node = cand[b * CC + tid];
        float2 s = d_S[node];
        logit = (s.x > 0.f) ? (s.y / s.x) : 0.f;
        sl[tid] = logit;
        outLogits[b * CC + tid] = logit;
    }
    red[tid] = (tid < CC) ? logit : -3.4e38f;
    __syncthreads();
    for (int st = 64; st > 0; st >>= 1) {
        if (tid < st) red[tid] = fmaxf(red[tid], red[tid + st]);
        __syncthreads();
    }
    float mx = red[0];
    __syncthreads();
    red[tid] = (tid < CC) ? expf(logit - mx) : 0.f;
    __syncthreads();
    for (int st = 64; st > 0; st >>= 1) {
        if (tid < st) red[tid] += red[tid + st];
        __syncthreads();
    }
    if (tid == 0) {
        int lab = label[b];
        d_lossPart[b] = -(sl[lab] - mx - logf(red[0]));
    }
}

__global__ void loss_kernel(float* __restrict__ outLoss) {
    float v = d_lossPart[threadIdx.x];  // 32 threads == BB
    #pragma unroll
    for (int o = 16; o > 0; o >>= 1) v += __shfl_xor_sync(0xffffffffu, v, o);
    if (threadIdx.x == 0) outLoss[0] = v;
}

// ---------------- launch --------------------------------------------------
extern "C" void kernel_launch(void* const* d_in, const int* in_sizes, int n_in,
                              void* d_out, int out_size) {
    const float* emb    = (const float*)d_in[0];
    const float* scores = (const float*)d_in[1];
    const float* Wl     = (const float*)d_in[2];
    const float* bl     = (const float*)d_in[3];
    const float* Wr     = (const float*)d_in[4];
    const float* br     = (const float*)d_in[5];
    const float* We     = (const float*)d_in[6];
    const float* be     = (const float*)d_in[7];
    const float* eemb   = (const float*)d_in[8];
    const int*   src    = (const int*)d_in[9];
    const int*   dst    = (const int*)d_in[10];
    const int*   et     = (const int*)d_in[11];
    const int*   cand   = (const int*)d_in[12];
    const int*   label  = (const int*)d_in[13];

    float* out = (float*)d_out;
    float* lossPtr;
    float* logitsPtr;
    if (out_size >= BB * CC + 1) {            // [loss, logits...] (tuple order)
        lossPtr = out;
        logitsPtr = out + 1;
    } else if (out_size == BB * CC) {         // logits only
        lossPtr = nullptr;
        logitsPtr = out;
    } else {                                  // loss only
        lossPtr = out;
        void* p = nullptr;
        cudaGetSymbolAddress(&p, d_logitsScratch);
        logitsPtr = (float*)p;
    }

    cudaFuncSetAttribute(gemm_mma_kernel,
                         cudaFuncAttributeMaxDynamicSharedMemorySize, S_TOTAL);

    prep1_kernel<<<1, HH>>>(We, be, eemb, bl, br);
    prep2_kernel<<<HH, HH>>>(Wl, Wr, bl, br);
    matA_kernel<<<HH, HH>>>(Wl, Wr);
    aux_kernel<<<NN / 8, 256>>>(emb);
    gemm_mma_kernel<<<dim3(NN / 128, 2), 256, S_TOTAL>>>();
    count_kernel<<<EE / 256, 256>>>(dst);
    scanA_kernel<<<NN / 256, 256>>>();
    scanB_kernel<<<1, 256>>>();
    scanC_kernel<<<NN / 256, 256>>>();
    scatter_kernel<<<EE / 256, 256>>>(src, dst, et);
    edge_csr_kernel<<<NN / 8, 256>>>(emb, scores);
    logits_kernel<<<BB, 128>>>(cand, label, logitsPtr);
    if (lossPtr) loss_kernel<<<1, 32>>>(lossPtr);
}